// round 1
// baseline (speedup 1.0000x reference)
#include <cuda_runtime.h>
#include <math.h>

#define D_MODEL 1024
#define N_HEADS 16
#define HEAD_DIM 64
#define BATCH 2
#define SEQL 2048
#define MROWS (BATCH * SEQL)   // 4096

// Scratch (allocation-free rule: device globals)
__device__ float g_q[MROWS * D_MODEL];
__device__ float g_k[MROWS * D_MODEL];
__device__ float g_v[MROWS * D_MODEL];
__device__ float g_att[MROWS * D_MODEL];

// ---------------------------------------------------------------------------
// SGEMM NT: C[m,n] = sum_k A[m,k] * B[n,k]   (A:[M,K] rowmajor, B:[N,K] rowmajor)
// 128x128 tile, BK=8, 256 threads, 8x8 per-thread register blocking.
// ---------------------------------------------------------------------------
#define BM 128
#define BN 128
#define BKG 8
#define TM 8
#define TN 8

__global__ __launch_bounds__(256) void sgemm_nt(const float* __restrict__ A,
                                                const float* __restrict__ B,
                                                float* __restrict__ C,
                                                int M, int N, int K) {
    __shared__ float As[BKG][BM + 4];
    __shared__ float Bs[BKG][BN + 4];

    const int tid = threadIdx.x;          // 0..255
    const int tx = tid & 15;              // 0..15 -> N
    const int ty = tid >> 4;              // 0..15 -> M
    const int lrow = tid >> 1;            // 0..127
    const int lcol = (tid & 1) << 2;      // 0 or 4

    const float* Aptr = A + (size_t)(blockIdx.y * BM + lrow) * K + lcol;
    const float* Bptr = B + (size_t)(blockIdx.x * BN + lrow) * K + lcol;

    float acc[TM][TN];
#pragma unroll
    for (int i = 0; i < TM; i++)
#pragma unroll
        for (int j = 0; j < TN; j++) acc[i][j] = 0.0f;

    for (int k0 = 0; k0 < K; k0 += BKG) {
        float4 a4 = *(const float4*)(Aptr + k0);
        float4 b4 = *(const float4*)(Bptr + k0);
        As[lcol + 0][lrow] = a4.x;
        As[lcol + 1][lrow] = a4.y;
        As[lcol + 2][lrow] = a4.z;
        As[lcol + 3][lrow] = a4.w;
        Bs[lcol + 0][lrow] = b4.x;
        Bs[lcol + 1][lrow] = b4.y;
        Bs[lcol + 2][lrow] = b4.z;
        Bs[lcol + 3][lrow] = b4.w;
        __syncthreads();

#pragma unroll
        for (int kk = 0; kk < BKG; kk++) {
            float a[TM], bb[TN];
            *(float4*)&a[0]  = *(const float4*)&As[kk][ty * TM];
            *(float4*)&a[4]  = *(const float4*)&As[kk][ty * TM + 4];
            *(float4*)&bb[0] = *(const float4*)&Bs[kk][tx * TN];
            *(float4*)&bb[4] = *(const float4*)&Bs[kk][tx * TN + 4];
#pragma unroll
            for (int i = 0; i < TM; i++)
#pragma unroll
                for (int j = 0; j < TN; j++) acc[i][j] += a[i] * bb[j];
        }
        __syncthreads();
    }

#pragma unroll
    for (int i = 0; i < TM; i++) {
        float* cp = C + (size_t)(blockIdx.y * BM + ty * TM + i) * N +
                    blockIdx.x * BN + tx * TN;
        *(float4*)cp       = make_float4(acc[i][0], acc[i][1], acc[i][2], acc[i][3]);
        *(float4*)(cp + 4) = make_float4(acc[i][4], acc[i][5], acc[i][6], acc[i][7]);
    }
}

// ---------------------------------------------------------------------------
// Flash attention, causal. One block = (q_tile 64, head, batch). 256 threads.
// Shared tiles (stride 68 to keep float4 alignment):
//   Qt[d][r], Kt[d][c]  -> S GEMM reads both as float4
//   St[c][r]            -> P stored col-major so PV GEMM reads float4
//   Vs[j][dim]          -> natural layout
// Online softmax: 4 threads per row, shfl combine.
// ---------------------------------------------------------------------------
#define AST 68

__global__ __launch_bounds__(256) void flash_attn(const float* __restrict__ Q,
                                                  const float* __restrict__ K,
                                                  const float* __restrict__ V,
                                                  float* __restrict__ O) {
    extern __shared__ float smf[];
    float* Qt   = smf;
    float* Kt   = smf + 64 * AST;
    float* St   = smf + 2 * 64 * AST;
    float* Vs   = smf + 3 * 64 * AST;
    float* rowm = smf + 4 * 64 * AST;
    float* rowl = rowm + 64;
    float* rsc  = rowl + 64;

    const int tid = threadIdx.x;
    const int tx = tid & 15;   // cols (keys / dims), 4 each
    const int ty = tid >> 4;   // rows (queries), 4 each
    const int qt = blockIdx.x;
    const int h  = blockIdx.y;
    const int b  = blockIdx.z;
    const int q0 = qt * 64;

    const size_t baseq = ((size_t)b * SEQL + q0) * D_MODEL + h * HEAD_DIM;

    if (tid < 64) {
        rowm[tid] = -3.0e38f;
        rowl[tid] = 0.0f;
    }

    // Load Q tile transposed: Qt[d][r]
#pragma unroll
    for (int it = 0; it < 4; it++) {
        int f = tid + it * 256;        // 0..1023 float4s
        int r = f >> 4;                // row 0..63
        int dblk = (f & 15) << 2;      // dim 0,4,...,60
        float4 v4 = *(const float4*)(Q + baseq + (size_t)r * D_MODEL + dblk);
        Qt[(dblk + 0) * AST + r] = v4.x;
        Qt[(dblk + 1) * AST + r] = v4.y;
        Qt[(dblk + 2) * AST + r] = v4.z;
        Qt[(dblk + 3) * AST + r] = v4.w;
    }

    float o[4][4];
#pragma unroll
    for (int i = 0; i < 4; i++)
#pragma unroll
        for (int j = 0; j < 4; j++) o[i][j] = 0.0f;

    for (int kt = 0; kt <= qt; kt++) {
        const int k0 = kt * 64;
        const size_t basek = ((size_t)b * SEQL + k0) * D_MODEL + h * HEAD_DIM;

        // Load K (transposed) and V (natural)
#pragma unroll
        for (int it = 0; it < 4; it++) {
            int f = tid + it * 256;
            int r = f >> 4;
            int dblk = (f & 15) << 2;
            float4 kv = *(const float4*)(K + basek + (size_t)r * D_MODEL + dblk);
            Kt[(dblk + 0) * AST + r] = kv.x;
            Kt[(dblk + 1) * AST + r] = kv.y;
            Kt[(dblk + 2) * AST + r] = kv.z;
            Kt[(dblk + 3) * AST + r] = kv.w;
            float4 vv = *(const float4*)(V + basek + (size_t)r * D_MODEL + dblk);
            *(float4*)&Vs[r * AST + dblk] = vv;
        }
        __syncthreads();

        // S = Q K^T
        float s[4][4];
#pragma unroll
        for (int i = 0; i < 4; i++)
#pragma unroll
            for (int j = 0; j < 4; j++) s[i][j] = 0.0f;

#pragma unroll 8
        for (int d = 0; d < 64; d++) {
            float4 a  = *(const float4*)&Qt[d * AST + ty * 4];
            float4 bb = *(const float4*)&Kt[d * AST + tx * 4];
            s[0][0] += a.x * bb.x; s[0][1] += a.x * bb.y; s[0][2] += a.x * bb.z; s[0][3] += a.x * bb.w;
            s[1][0] += a.y * bb.x; s[1][1] += a.y * bb.y; s[1][2] += a.y * bb.z; s[1][3] += a.y * bb.w;
            s[2][0] += a.z * bb.x; s[2][1] += a.z * bb.y; s[2][2] += a.z * bb.z; s[2][3] += a.z * bb.w;
            s[3][0] += a.w * bb.x; s[3][1] += a.w * bb.y; s[3][2] += a.w * bb.z; s[3][3] += a.w * bb.w;
        }

        // scale + causal mask (matches ref: masked entries = -10000.0, exp underflows to 0)
        const bool diag = (kt == qt);
#pragma unroll
        for (int i = 0; i < 4; i++)
#pragma unroll
            for (int j = 0; j < 4; j++) {
                float val = s[i][j] * 0.125f;   // 1/sqrt(64)
                if (diag && (tx * 4 + j) > (ty * 4 + i)) val = -10000.0f;
                St[(tx * 4 + j) * AST + (ty * 4 + i)] = val;
            }
        __syncthreads();

        // Online softmax: 4 threads per row
        {
            const int r = tid >> 2;
            const int part = tid & 3;
            const float mold = rowm[r];
            float mx = -3.0e38f;
#pragma unroll
            for (int cc = 0; cc < 16; cc++)
                mx = fmaxf(mx, St[(part * 16 + cc) * AST + r]);
            mx = fmaxf(mx, __shfl_xor_sync(0xffffffffu, mx, 1));
            mx = fmaxf(mx, __shfl_xor_sync(0xffffffffu, mx, 2));
            const float mnew = fmaxf(mold, mx);
            float sum = 0.0f;
#pragma unroll
            for (int cc = 0; cc < 16; cc++) {
                int c = part * 16 + cc;
                float e = __expf(St[c * AST + r] - mnew);
                St[c * AST + r] = e;
                sum += e;
            }
            sum += __shfl_xor_sync(0xffffffffu, sum, 1);
            sum += __shfl_xor_sync(0xffffffffu, sum, 2);
            if (part == 0) {
                float fsc = __expf(mold - mnew);
                rsc[r] = fsc;
                rowl[r] = rowl[r] * fsc + sum;
                rowm[r] = mnew;
            }
        }
        __syncthreads();

        // Rescale accumulators, then O += P @ V
        float fs[4];
#pragma unroll
        for (int i = 0; i < 4; i++) fs[i] = rsc[ty * 4 + i];
#pragma unroll
        for (int i = 0; i < 4; i++)
#pragma unroll
            for (int j = 0; j < 4; j++) o[i][j] *= fs[i];

#pragma unroll 8
        for (int jj = 0; jj < 64; jj++) {
            float4 a  = *(const float4*)&St[jj * AST + ty * 4];
            float4 bb = *(const float4*)&Vs[jj * AST + tx * 4];
            o[0][0] += a.x * bb.x; o[0][1] += a.x * bb.y; o[0][2] += a.x * bb.z; o[0][3] += a.x * bb.w;
            o[1][0] += a.y * bb.x; o[1][1] += a.y * bb.y; o[1][2] += a.y * bb.z; o[1][3] += a.y * bb.w;
            o[2][0] += a.z * bb.x; o[2][1] += a.z * bb.y; o[2][2] += a.z * bb.z; o[2][3] += a.z * bb.w;
            o[3][0] += a.w * bb.x; o[3][1] += a.w * bb.y; o[3][2] += a.w * bb.z; o[3][3] += a.w * bb.w;
        }
        __syncthreads();   // protect Kt/Vs/St before next tile's loads
    }

    // Epilogue: divide by l, store [B,S,H*dh]
#pragma unroll
    for (int i = 0; i < 4; i++) {
        float linv = 1.0f / rowl[ty * 4 + i];
        float4 res = make_float4(o[i][0] * linv, o[i][1] * linv,
                                 o[i][2] * linv, o[i][3] * linv);
        *(float4*)(O + baseq + (size_t)(ty * 4 + i) * D_MODEL + tx * 4) = res;
    }
}

// ---------------------------------------------------------------------------
extern "C" void kernel_launch(void* const* d_in, const int* in_sizes, int n_in,
                              void* d_out, int out_size) {
    const float* x  = (const float*)d_in[0];
    const float* wq = (const float*)d_in[1];
    const float* wk = (const float*)d_in[2];
    const float* wv = (const float*)d_in[3];
    const float* wo = (const float*)d_in[4];
    float* out = (float*)d_out;

    float *q, *k, *v, *att;
    cudaGetSymbolAddress((void**)&q, g_q);
    cudaGetSymbolAddress((void**)&k, g_k);
    cudaGetSymbolAddress((void**)&v, g_v);
    cudaGetSymbolAddress((void**)&att, g_att);

    const int smem_attn = (4 * 64 * AST + 3 * 64) * (int)sizeof(float);  // 70400 B
    cudaFuncSetAttribute(flash_attn, cudaFuncAttributeMaxDynamicSharedMemorySize,
                         smem_attn);

    dim3 gg(D_MODEL / BN, MROWS / BM);   // (8, 32)
    sgemm_nt<<<gg, 256>>>(x, wq, q, MROWS, D_MODEL, D_MODEL);
    sgemm_nt<<<gg, 256>>>(x, wk, k, MROWS, D_MODEL, D_MODEL);
    sgemm_nt<<<gg, 256>>>(x, wv, v, MROWS, D_MODEL, D_MODEL);

    flash_attn<<<dim3(SEQL / 64, N_HEADS, BATCH), 256, smem_attn>>>(q, k, v, att);

    sgemm_nt<<<gg, 256>>>(att, wo, out, MROWS, D_MODEL, D_MODEL);
}

// round 4
// speedup vs baseline: 1.5105x; 1.5105x over previous
#include <cuda_runtime.h>
#include <cuda_bf16.h>
#include <cstdint>
#include <math.h>

#define D_MODEL 1024
#define N_HEADS 16
#define HEAD_DIM 64
#define BATCH 2
#define SEQL 2048
#define MROWS (BATCH * SEQL)   // 4096

// ---------------- scratch (device globals: allocation-free rule) -----------
__device__ float g_q[MROWS * D_MODEL];
__device__ float g_k[MROWS * D_MODEL];
__device__ float g_v[MROWS * D_MODEL];
__device__ float g_att[MROWS * D_MODEL];

__device__ __nv_bfloat16 g_xh[MROWS * D_MODEL];
__device__ __nv_bfloat16 g_xl[MROWS * D_MODEL];
__device__ __nv_bfloat16 g_ath[MROWS * D_MODEL];
__device__ __nv_bfloat16 g_atl[MROWS * D_MODEL];
__device__ __nv_bfloat16 g_wqh[D_MODEL * D_MODEL];
__device__ __nv_bfloat16 g_wql[D_MODEL * D_MODEL];
__device__ __nv_bfloat16 g_wkh[D_MODEL * D_MODEL];
__device__ __nv_bfloat16 g_wkl[D_MODEL * D_MODEL];
__device__ __nv_bfloat16 g_wvh[D_MODEL * D_MODEL];
__device__ __nv_bfloat16 g_wvl[D_MODEL * D_MODEL];
__device__ __nv_bfloat16 g_woh[D_MODEL * D_MODEL];
__device__ __nv_bfloat16 g_wol[D_MODEL * D_MODEL];

// ---------------- helpers ---------------------------------------------------
__device__ __forceinline__ uint32_t smem_to_u32(const void* p) {
    uint32_t a;
    asm("{ .reg .u64 t; cvta.to.shared.u64 t, %1; cvt.u32.u64 %0, t; }" : "=r"(a) : "l"(p));
    return a;
}

__device__ __forceinline__ void ldsm4(uint32_t* r, uint32_t addr) {
    asm volatile("ldmatrix.sync.aligned.m8n8.x4.shared.b16 {%0,%1,%2,%3}, [%4];"
                 : "=r"(r[0]), "=r"(r[1]), "=r"(r[2]), "=r"(r[3]) : "r"(addr));
}

__device__ __forceinline__ void mma16816(float* d, const uint32_t* a, const uint32_t* b) {
    asm volatile(
        "mma.sync.aligned.m16n8k16.row.col.f32.bf16.bf16.f32 "
        "{%0,%1,%2,%3}, {%4,%5,%6,%7}, {%8,%9}, {%0,%1,%2,%3};"
        : "+f"(d[0]), "+f"(d[1]), "+f"(d[2]), "+f"(d[3])
        : "r"(a[0]), "r"(a[1]), "r"(a[2]), "r"(a[3]), "r"(b[0]), "r"(b[1]));
}

// ---------------------------------------------------------------------------
// split fp32 -> (bf16 hi, bf16 lo)
// ---------------------------------------------------------------------------
__global__ __launch_bounds__(256) void split_bf16_k(const float4* __restrict__ in,
                                                    __nv_bfloat162* __restrict__ hi,
                                                    __nv_bfloat162* __restrict__ lo,
                                                    int n4) {
    int i = blockIdx.x * blockDim.x + threadIdx.x;
    if (i >= n4) return;
    float4 v = in[i];
    __nv_bfloat16 h0 = __float2bfloat16(v.x);
    __nv_bfloat16 h1 = __float2bfloat16(v.y);
    __nv_bfloat16 h2 = __float2bfloat16(v.z);
    __nv_bfloat16 h3 = __float2bfloat16(v.w);
    __nv_bfloat16 l0 = __float2bfloat16(v.x - __bfloat162float(h0));
    __nv_bfloat16 l1 = __float2bfloat16(v.y - __bfloat162float(h1));
    __nv_bfloat16 l2 = __float2bfloat16(v.z - __bfloat162float(h2));
    __nv_bfloat16 l3 = __float2bfloat16(v.w - __bfloat162float(h3));
    hi[2 * i]     = __nv_bfloat162(h0, h1);
    hi[2 * i + 1] = __nv_bfloat162(h2, h3);
    lo[2 * i]     = __nv_bfloat162(l0, l1);
    lo[2 * i + 1] = __nv_bfloat162(l2, l3);
}

// ---------------------------------------------------------------------------
// HMMA split-bf16 GEMM-NT: C[m,n] = sum_k A[m,k]*B[n,k]  (fp32-accurate)
// CTA 128x128, BK=32 bf16. 8 warps (2x4), each warp 64x32 via m16n8k16.
// SMEM rows padded to 80B (stride 80 mod 128 -> conflict-free ldmatrix).
// Double-buffered, one __syncthreads per K-tile.
// ---------------------------------------------------------------------------
#define GBK 32
#define GKT (D_MODEL / GBK)          // 32 k-tiles
#define ARR_B 10240                  // 128 rows * 80 B
#define STG_B (4 * ARR_B)            // Ah | Al | Bh | Bl = 40960
#define GEMM_SMEM (2 * STG_B)        // 81920

__global__ __launch_bounds__(256, 1) void gemm_mma_nt(
    const __nv_bfloat16* __restrict__ Ah, const __nv_bfloat16* __restrict__ Al,
    const __nv_bfloat16* __restrict__ Bh, const __nv_bfloat16* __restrict__ Bl,
    float* __restrict__ C, int M, int N, int K) {
    extern __shared__ char smc[];
    const uint32_t sb = smem_to_u32(smc);

    const int tid = threadIdx.x;
    const int wid = tid >> 5;
    const int lane = tid & 31;
    const int wm = wid >> 2;          // 0..1 -> m offset wm*64
    const int wn = wid & 3;           // 0..3 -> n offset wn*32
    const int m0 = blockIdx.y * 128;
    const int n0 = blockIdx.x * 128;

    // global load mapping: row = tid>>1 (0..127), half-offset (tid&1)*16
    const int lrow = tid >> 1;
    const int lhof = (tid & 1) * 16;
    const __nv_bfloat16* pAh = Ah + (size_t)(m0 + lrow) * K + lhof;
    const __nv_bfloat16* pAl = Al + (size_t)(m0 + lrow) * K + lhof;
    const __nv_bfloat16* pBh = Bh + (size_t)(n0 + lrow) * K + lhof;
    const __nv_bfloat16* pBl = Bl + (size_t)(n0 + lrow) * K + lhof;
    const uint32_t sdst = lrow * 80 + (tid & 1) * 32;

    // ldmatrix address bases (within an array)
    const uint32_t aoff = (uint32_t)((wm * 64 + (lane & 15)) * 80 + (lane >> 4) * 16);
    const int j8 = lane >> 3;
    const uint32_t boff = (uint32_t)((wn * 32 + ((j8 >> 1) << 3) + (lane & 7)) * 80 + (j8 & 1) * 16);

    float acc[4][4][4];
#pragma unroll
    for (int a = 0; a < 4; a++)
#pragma unroll
        for (int b = 0; b < 4; b++)
#pragma unroll
            for (int c = 0; c < 4; c++) acc[a][b][c] = 0.0f;

    uint4 rg[8];
    // prefetch tile 0
    rg[0] = *(const uint4*)(pAh);      rg[1] = *(const uint4*)(pAh + 8);
    rg[2] = *(const uint4*)(pAl);      rg[3] = *(const uint4*)(pAl + 8);
    rg[4] = *(const uint4*)(pBh);      rg[5] = *(const uint4*)(pBh + 8);
    rg[6] = *(const uint4*)(pBl);      rg[7] = *(const uint4*)(pBl + 8);

    for (int t = 0; t < GKT; t++) {
        // store staged regs -> smem buffer t&1
        const uint32_t bufo = (uint32_t)((t & 1) * STG_B) + sdst;
        *(uint4*)(smc + bufo + 0 * ARR_B)      = rg[0];
        *(uint4*)(smc + bufo + 0 * ARR_B + 16) = rg[1];
        *(uint4*)(smc + bufo + 1 * ARR_B)      = rg[2];
        *(uint4*)(smc + bufo + 1 * ARR_B + 16) = rg[3];
        *(uint4*)(smc + bufo + 2 * ARR_B)      = rg[4];
        *(uint4*)(smc + bufo + 2 * ARR_B + 16) = rg[5];
        *(uint4*)(smc + bufo + 3 * ARR_B)      = rg[6];
        *(uint4*)(smc + bufo + 3 * ARR_B + 16) = rg[7];
        __syncthreads();

        // prefetch next tile
        if (t + 1 < GKT) {
            const int go = (t + 1) * GBK;
            rg[0] = *(const uint4*)(pAh + go);      rg[1] = *(const uint4*)(pAh + go + 8);
            rg[2] = *(const uint4*)(pAl + go);      rg[3] = *(const uint4*)(pAl + go + 8);
            rg[4] = *(const uint4*)(pBh + go);      rg[5] = *(const uint4*)(pBh + go + 8);
            rg[6] = *(const uint4*)(pBl + go);      rg[7] = *(const uint4*)(pBl + go + 8);
        }

        // compute from buffer t&1
        const uint32_t stg = sb + (uint32_t)((t & 1) * STG_B);
#pragma unroll
        for (int ks = 0; ks < 2; ks++) {
            uint32_t ah[4][4], al[4][4];
#pragma unroll
            for (int mt = 0; mt < 4; mt++) {
                ldsm4(ah[mt], stg + 0 * ARR_B + aoff + mt * 1280 + ks * 32);
                ldsm4(al[mt], stg + 1 * ARR_B + aoff + mt * 1280 + ks * 32);
            }
            uint32_t bh[4][2], bl[4][2];
#pragma unroll
            for (int bt = 0; bt < 2; bt++) {
                uint32_t tmp[4];
                ldsm4(tmp, stg + 2 * ARR_B + boff + bt * 1280 + ks * 32);
                bh[2 * bt][0] = tmp[0]; bh[2 * bt][1] = tmp[1];
                bh[2 * bt + 1][0] = tmp[2]; bh[2 * bt + 1][1] = tmp[3];
                ldsm4(tmp, stg + 3 * ARR_B + boff + bt * 1280 + ks * 32);
                bl[2 * bt][0] = tmp[0]; bl[2 * bt][1] = tmp[1];
                bl[2 * bt + 1][0] = tmp[2]; bl[2 * bt + 1][1] = tmp[3];
            }
#pragma unroll
            for (int mt = 0; mt < 4; mt++)
#pragma unroll
                for (int nt = 0; nt < 4; nt++) {
                    mma16816(acc[mt][nt], ah[mt], bh[nt]);
                    mma16816(acc[mt][nt], ah[mt], bl[nt]);
                    mma16816(acc[mt][nt], al[mt], bh[nt]);
                }
        }
        __syncthreads();
    }

    // epilogue
    const int gr = lane >> 2;
    const int gc = (lane & 3) * 2;
#pragma unroll
    for (int mt = 0; mt < 4; mt++) {
        const int row = m0 + wm * 64 + mt * 16 + gr;
#pragma unroll
        for (int nt = 0; nt < 4; nt++) {
            const int col = n0 + wn * 32 + nt * 8 + gc;
            *(float2*)&C[(size_t)row * N + col] =
                make_float2(acc[mt][nt][0], acc[mt][nt][1]);
            *(float2*)&C[(size_t)(row + 8) * N + col] =
                make_float2(acc[mt][nt][2], acc[mt][nt][3]);
        }
    }
}

// ---------------------------------------------------------------------------
// Flash attention, causal (round-1 version, unchanged). 64x64 tiles, fp32.
// ---------------------------------------------------------------------------
#define AST 68

__global__ __launch_bounds__(256) void flash_attn(const float* __restrict__ Q,
                                                  const float* __restrict__ K,
                                                  const float* __restrict__ V,
                                                  float* __restrict__ O) {
    extern __shared__ float smf[];
    float* Qt   = smf;
    float* Kt   = smf + 64 * AST;
    float* St   = smf + 2 * 64 * AST;
    float* Vs   = smf + 3 * 64 * AST;
    float* rowm = smf + 4 * 64 * AST;
    float* rowl = rowm + 64;
    float* rsc  = rowl + 64;

    const int tid = threadIdx.x;
    const int tx = tid & 15;
    const int ty = tid >> 4;
    const int qt = blockIdx.x;
    const int h  = blockIdx.y;
    const int b  = blockIdx.z;
    const int q0 = qt * 64;

    const size_t baseq = ((size_t)b * SEQL + q0) * D_MODEL + h * HEAD_DIM;

    if (tid < 64) {
        rowm[tid] = -3.0e38f;
        rowl[tid] = 0.0f;
    }

#pragma unroll
    for (int it = 0; it < 4; it++) {
        int f = tid + it * 256;
        int r = f >> 4;
        int dblk = (f & 15) << 2;
        float4 v4 = *(const float4*)(Q + baseq + (size_t)r * D_MODEL + dblk);
        Qt[(dblk + 0) * AST + r] = v4.x;
        Qt[(dblk + 1) * AST + r] = v4.y;
        Qt[(dblk + 2) * AST + r] = v4.z;
        Qt[(dblk + 3) * AST + r] = v4.w;
    }

    float o[4][4];
#pragma unroll
    for (int i = 0; i < 4; i++)
#pragma unroll
        for (int j = 0; j < 4; j++) o[i][j] = 0.0f;

    for (int kt = 0; kt <= qt; kt++) {
        const int k0 = kt * 64;
        const size_t basek = ((size_t)b * SEQL + k0) * D_MODEL + h * HEAD_DIM;

#pragma unroll
        for (int it = 0; it < 4; it++) {
            int f = tid + it * 256;
            int r = f >> 4;
            int dblk = (f & 15) << 2;
            float4 kv = *(const float4*)(K + basek + (size_t)r * D_MODEL + dblk);
            Kt[(dblk + 0) * AST + r] = kv.x;
            Kt[(dblk + 1) * AST + r] = kv.y;
            Kt[(dblk + 2) * AST + r] = kv.z;
            Kt[(dblk + 3) * AST + r] = kv.w;
            float4 vv = *(const float4*)(V + basek + (size_t)r * D_MODEL + dblk);
            *(float4*)&Vs[r * AST + dblk] = vv;
        }
        __syncthreads();

        float s[4][4];
#pragma unroll
        for (int i = 0; i < 4; i++)
#pragma unroll
            for (int j = 0; j < 4; j++) s[i][j] = 0.0f;

#pragma unroll 8
        for (int d = 0; d < 64; d++) {
            float4 a  = *(const float4*)&Qt[d * AST + ty * 4];
            float4 bb = *(const float4*)&Kt[d * AST + tx * 4];
            s[0][0] += a.x * bb.x; s[0][1] += a.x * bb.y; s[0][2] += a.x * bb.z; s[0][3] += a.x * bb.w;
            s[1][0] += a.y * bb.x; s[1][1] += a.y * bb.y; s[1][2] += a.y * bb.z; s[1][3] += a.y * bb.w;
            s[2][0] += a.z * bb.x; s[2][1] += a.z * bb.y; s[2][2] += a.z * bb.z; s[2][3] += a.z * bb.w;
            s[3][0] += a.w * bb.x; s[3][1] += a.w * bb.y; s[3][2] += a.w * bb.z; s[3][3] += a.w * bb.w;
        }

        const bool diag = (kt == qt);
#pragma unroll
        for (int i = 0; i < 4; i++)
#pragma unroll
            for (int j = 0; j < 4; j++) {
                float val = s[i][j] * 0.125f;
                if (diag && (tx * 4 + j) > (ty * 4 + i)) val = -10000.0f;
                St[(tx * 4 + j) * AST + (ty * 4 + i)] = val;
            }
        __syncthreads();

        {
            const int r = tid >> 2;
            const int part = tid & 3;
            const float mold = rowm[r];
            float mx = -3.0e38f;
#pragma unroll
            for (int cc = 0; cc < 16; cc++)
                mx = fmaxf(mx, St[(part * 16 + cc) * AST + r]);
            mx = fmaxf(mx, __shfl_xor_sync(0xffffffffu, mx, 1));
            mx = fmaxf(mx, __shfl_xor_sync(0xffffffffu, mx, 2));
            const float mnew = fmaxf(mold, mx);
            float sum = 0.0f;
#pragma unroll
            for (int cc = 0; cc < 16; cc++) {
                int c = part * 16 + cc;
                float e = __expf(St[c * AST + r] - mnew);
                St[c * AST + r] = e;
                sum += e;
            }
            sum += __shfl_xor_sync(0xffffffffu, sum, 1);
            sum += __shfl_xor_sync(0xffffffffu, sum, 2);
            if (part == 0) {
                float fsc = __expf(mold - mnew);
                rsc[r] = fsc;
                rowl[r] = rowl[r] * fsc + sum;
                rowm[r] = mnew;
            }
        }
        __syncthreads();

        float fs[4];
#pragma unroll
        for (int i = 0; i < 4; i++) fs[i] = rsc[ty * 4 + i];
#pragma unroll
        for (int i = 0; i < 4; i++)
#pragma unroll
            for (int j = 0; j < 4; j++) o[i][j] *= fs[i];

#pragma unroll 8
        for (int jj = 0; jj < 64; jj++) {
            float4 a  = *(const float4*)&St[jj * AST + ty * 4];
            float4 bb = *(const float4*)&Vs[jj * AST + tx * 4];
            o[0][0] += a.x * bb.x; o[0][1] += a.x * bb.y; o[0][2] += a.x * bb.z; o[0][3] += a.x * bb.w;
            o[1][0] += a.y * bb.x; o[1][1] += a.y * bb.y; o[1][2] += a.y * bb.z; o[1][3] += a.y * bb.w;
            o[2][0] += a.z * bb.x; o[2][1] += a.z * bb.y; o[2][2] += a.z * bb.z; o[2][3] += a.z * bb.w;
            o[3][0] += a.w * bb.x; o[3][1] += a.w * bb.y; o[3][2] += a.w * bb.z; o[3][3] += a.w * bb.w;
        }
        __syncthreads();
    }

#pragma unroll
    for (int i = 0; i < 4; i++) {
        float linv = 1.0f / rowl[ty * 4 + i];
        float4 res = make_float4(o[i][0] * linv, o[i][1] * linv,
                                 o[i][2] * linv, o[i][3] * linv);
        *(float4*)(O + baseq + (size_t)(ty * 4 + i) * D_MODEL + tx * 4) = res;
    }
}

// ---------------------------------------------------------------------------
extern "C" void kernel_launch(void* const* d_in, const int* in_sizes, int n_in,
                              void* d_out, int out_size) {
    const float* x  = (const float*)d_in[0];
    const float* wq = (const float*)d_in[1];
    const float* wk = (const float*)d_in[2];
    const float* wv = (const float*)d_in[3];
    const float* wo = (const float*)d_in[4];
    float* out = (float*)d_out;

    float *q, *k, *v, *att;
    cudaGetSymbolAddress((void**)&q, g_q);
    cudaGetSymbolAddress((void**)&k, g_k);
    cudaGetSymbolAddress((void**)&v, g_v);
    cudaGetSymbolAddress((void**)&att, g_att);

    __nv_bfloat16 *xh, *xl, *ath, *atl, *wqh, *wql, *wkh, *wkl, *wvh, *wvl, *woh, *wol;
    cudaGetSymbolAddress((void**)&xh, g_xh);   cudaGetSymbolAddress((void**)&xl, g_xl);
    cudaGetSymbolAddress((void**)&ath, g_ath); cudaGetSymbolAddress((void**)&atl, g_atl);
    cudaGetSymbolAddress((void**)&wqh, g_wqh); cudaGetSymbolAddress((void**)&wql, g_wql);
    cudaGetSymbolAddress((void**)&wkh, g_wkh); cudaGetSymbolAddress((void**)&wkl, g_wkl);
    cudaGetSymbolAddress((void**)&wvh, g_wvh); cudaGetSymbolAddress((void**)&wvl, g_wvl);
    cudaGetSymbolAddress((void**)&woh, g_woh); cudaGetSymbolAddress((void**)&wol, g_wol);

    const int smem_attn = (4 * 64 * AST + 3 * 64) * (int)sizeof(float);
    cudaFuncSetAttribute(flash_attn, cudaFuncAttributeMaxDynamicSharedMemorySize, smem_attn);
    cudaFuncSetAttribute(gemm_mma_nt, cudaFuncAttributeMaxDynamicSharedMemorySize, GEMM_SMEM);

    const int nx4 = MROWS * D_MODEL / 4;
    const int nw4 = D_MODEL * D_MODEL / 4;

    split_bf16_k<<<(nx4 + 255) / 256, 256>>>((const float4*)x, (__nv_bfloat162*)xh, (__nv_bfloat162*)xl, nx4);
    split_bf16_k<<<(nw4 + 255) / 256, 256>>>((const float4*)wq, (__nv_bfloat162*)wqh, (__nv_bfloat162*)wql, nw4);
    split_bf16_k<<<(nw4 + 255) / 256, 256>>>((const float4*)wk, (__nv_bfloat162*)wkh, (__nv_bfloat162*)wkl, nw4);
    split_bf16_k<<<(nw4 + 255) / 256, 256>>>((const float4*)wv, (__nv_bfloat162*)wvh, (__nv_bfloat162*)wvl, nw4);
    split_bf16_k<<<(nw4 + 255) / 256, 256>>>((const float4*)wo, (__nv_bfloat162*)woh, (__nv_bfloat162*)wol, nw4);

    dim3 gg(D_MODEL / 128, MROWS / 128);   // (8, 32)
    gemm_mma_nt<<<gg, 256, GEMM_SMEM>>>(xh, xl, wqh, wql, q, MROWS, D_MODEL, D_MODEL);
    gemm_mma_nt<<<gg, 256, GEMM_SMEM>>>(xh, xl, wkh, wkl, k, MROWS, D_MODEL, D_MODEL);
    gemm_mma_nt<<<gg, 256, GEMM_SMEM>>>(xh, xl, wvh, wvl, v, MROWS, D_MODEL, D_MODEL);

    flash_attn<<<dim3(SEQL / 64, N_HEADS, BATCH), 256, smem_attn>>>(q, k, v, att);

    split_bf16_k<<<(nx4 + 255) / 256, 256>>>((const float4*)att, (__nv_bfloat162*)ath, (__nv_bfloat162*)atl, nx4);
    gemm_mma_nt<<<gg, 256, GEMM_SMEM>>>(ath, atl, woh, wol, out, MROWS, D_MODEL, D_MODEL);
}

// round 5
// speedup vs baseline: 2.5876x; 1.7131x over previous
#include <cuda_runtime.h>
#include <cuda_bf16.h>
#include <cstdint>
#include <math.h>

#define D_MODEL 1024
#define N_HEADS 16
#define HEAD_DIM 64
#define BATCH 2
#define SEQL 2048
#define MROWS (BATCH * SEQL)   // 4096

// ---------------- scratch (device globals: allocation-free rule) -----------
__device__ __nv_bfloat16 g_xh[MROWS * D_MODEL];
__device__ __nv_bfloat16 g_xl[MROWS * D_MODEL];
__device__ __nv_bfloat16 g_qh[MROWS * D_MODEL];
__device__ __nv_bfloat16 g_ql[MROWS * D_MODEL];
__device__ __nv_bfloat16 g_kh[MROWS * D_MODEL];
__device__ __nv_bfloat16 g_kl[MROWS * D_MODEL];
__device__ __nv_bfloat16 g_vh[MROWS * D_MODEL];
__device__ __nv_bfloat16 g_vl[MROWS * D_MODEL];
__device__ __nv_bfloat16 g_ath[MROWS * D_MODEL];
__device__ __nv_bfloat16 g_atl[MROWS * D_MODEL];
__device__ __nv_bfloat16 g_wqh[D_MODEL * D_MODEL];
__device__ __nv_bfloat16 g_wql[D_MODEL * D_MODEL];
__device__ __nv_bfloat16 g_wkh[D_MODEL * D_MODEL];
__device__ __nv_bfloat16 g_wkl[D_MODEL * D_MODEL];
__device__ __nv_bfloat16 g_wvh[D_MODEL * D_MODEL];
__device__ __nv_bfloat16 g_wvl[D_MODEL * D_MODEL];
__device__ __nv_bfloat16 g_woh[D_MODEL * D_MODEL];
__device__ __nv_bfloat16 g_wol[D_MODEL * D_MODEL];

// ---------------- helpers ---------------------------------------------------
__device__ __forceinline__ uint32_t smem_to_u32(const void* p) {
    uint32_t a;
    asm("{ .reg .u64 t; cvta.to.shared.u64 t, %1; cvt.u32.u64 %0, t; }" : "=r"(a) : "l"(p));
    return a;
}

__device__ __forceinline__ void ldsm4(uint32_t* r, uint32_t addr) {
    asm volatile("ldmatrix.sync.aligned.m8n8.x4.shared.b16 {%0,%1,%2,%3}, [%4];"
                 : "=r"(r[0]), "=r"(r[1]), "=r"(r[2]), "=r"(r[3]) : "r"(addr));
}

__device__ __forceinline__ void ldsm4t(uint32_t* r, uint32_t addr) {
    asm volatile("ldmatrix.sync.aligned.m8n8.x4.trans.shared.b16 {%0,%1,%2,%3}, [%4];"
                 : "=r"(r[0]), "=r"(r[1]), "=r"(r[2]), "=r"(r[3]) : "r"(addr));
}

__device__ __forceinline__ void mma16816(float* d, const uint32_t* a, const uint32_t* b) {
    asm volatile(
        "mma.sync.aligned.m16n8k16.row.col.f32.bf16.bf16.f32 "
        "{%0,%1,%2,%3}, {%4,%5,%6,%7}, {%8,%9}, {%0,%1,%2,%3};"
        : "+f"(d[0]), "+f"(d[1]), "+f"(d[2]), "+f"(d[3])
        : "r"(a[0]), "r"(a[1]), "r"(a[2]), "r"(a[3]), "r"(b[0]), "r"(b[1]));
}

// split (x,y) fp32 -> packed bf16x2 hi + packed bf16x2 lo (low half = x)
__device__ __forceinline__ void split2(float x, float y, uint32_t& hi, uint32_t& lo) {
    __nv_bfloat16 hx = __float2bfloat16(x), hy = __float2bfloat16(y);
    __nv_bfloat16 lx = __float2bfloat16(x - __bfloat162float(hx));
    __nv_bfloat16 ly = __float2bfloat16(y - __bfloat162float(hy));
    __nv_bfloat162 H(hx, hy), L(lx, ly);
    hi = *(uint32_t*)&H;
    lo = *(uint32_t*)&L;
}

__device__ __forceinline__ void store_split2(__nv_bfloat16* H, __nv_bfloat16* L,
                                             size_t idx, float x, float y) {
    uint32_t hi, lo;
    split2(x, y, hi, lo);
    *(uint32_t*)(H + idx) = hi;
    *(uint32_t*)(L + idx) = lo;
}

// ---------------------------------------------------------------------------
// split fp32 -> (bf16 hi, bf16 lo)
// ---------------------------------------------------------------------------
__global__ __launch_bounds__(256) void split_bf16_k(const float4* __restrict__ in,
                                                    __nv_bfloat162* __restrict__ hi,
                                                    __nv_bfloat162* __restrict__ lo,
                                                    int n4) {
    int i = blockIdx.x * blockDim.x + threadIdx.x;
    if (i >= n4) return;
    float4 v = in[i];
    uint32_t h0, l0, h1, l1;
    split2(v.x, v.y, h0, l0);
    split2(v.z, v.w, h1, l1);
    *(uint32_t*)&hi[2 * i]     = h0;
    *(uint32_t*)&hi[2 * i + 1] = h1;
    *(uint32_t*)&lo[2 * i]     = l0;
    *(uint32_t*)&lo[2 * i + 1] = l1;
}

// ---------------------------------------------------------------------------
// HMMA split-bf16 GEMM-NT: C[m,n] = sum_k A[m,k]*B[n,k]  (fp32-accurate)
// CTA 128x128, BK=32 bf16. 8 warps (2x4), each warp 64x32 via m16n8k16.
// SPLIT=true  -> write result as bf16 hi/lo pair (Ch, Cl)
// SPLIT=false -> write fp32 to C
// ---------------------------------------------------------------------------
#define GBK 32
#define GKT (D_MODEL / GBK)          // 32 k-tiles
#define ARR_B 10240                  // 128 rows * 80 B
#define STG_B (4 * ARR_B)            // Ah | Al | Bh | Bl = 40960
#define GEMM_SMEM (2 * STG_B)        // 81920

template <bool SPLIT>
__global__ __launch_bounds__(256, 1) void gemm_mma_nt(
    const __nv_bfloat16* __restrict__ Ah, const __nv_bfloat16* __restrict__ Al,
    const __nv_bfloat16* __restrict__ Bh, const __nv_bfloat16* __restrict__ Bl,
    float* __restrict__ C, __nv_bfloat16* __restrict__ Ch, __nv_bfloat16* __restrict__ Cl,
    int M, int N, int K) {
    extern __shared__ char smc[];
    const uint32_t sb = smem_to_u32(smc);

    const int tid = threadIdx.x;
    const int wid = tid >> 5;
    const int lane = tid & 31;
    const int wm = wid >> 2;
    const int wn = wid & 3;
    const int m0 = blockIdx.y * 128;
    const int n0 = blockIdx.x * 128;

    const int lrow = tid >> 1;
    const int lhof = (tid & 1) * 16;
    const __nv_bfloat16* pAh = Ah + (size_t)(m0 + lrow) * K + lhof;
    const __nv_bfloat16* pAl = Al + (size_t)(m0 + lrow) * K + lhof;
    const __nv_bfloat16* pBh = Bh + (size_t)(n0 + lrow) * K + lhof;
    const __nv_bfloat16* pBl = Bl + (size_t)(n0 + lrow) * K + lhof;
    const uint32_t sdst = lrow * 80 + (tid & 1) * 32;

    const uint32_t aoff = (uint32_t)((wm * 64 + (lane & 15)) * 80 + (lane >> 4) * 16);
    const int j8 = lane >> 3;
    const uint32_t boff = (uint32_t)((wn * 32 + ((j8 >> 1) << 3) + (lane & 7)) * 80 + (j8 & 1) * 16);

    float acc[4][4][4];
#pragma unroll
    for (int a = 0; a < 4; a++)
#pragma unroll
        for (int b = 0; b < 4; b++)
#pragma unroll
            for (int c = 0; c < 4; c++) acc[a][b][c] = 0.0f;

    uint4 rg[8];
    rg[0] = *(const uint4*)(pAh);      rg[1] = *(const uint4*)(pAh + 8);
    rg[2] = *(const uint4*)(pAl);      rg[3] = *(const uint4*)(pAl + 8);
    rg[4] = *(const uint4*)(pBh);      rg[5] = *(const uint4*)(pBh + 8);
    rg[6] = *(const uint4*)(pBl);      rg[7] = *(const uint4*)(pBl + 8);

    for (int t = 0; t < GKT; t++) {
        const uint32_t bufo = (uint32_t)((t & 1) * STG_B) + sdst;
        *(uint4*)(smc + bufo + 0 * ARR_B)      = rg[0];
        *(uint4*)(smc + bufo + 0 * ARR_B + 16) = rg[1];
        *(uint4*)(smc + bufo + 1 * ARR_B)      = rg[2];
        *(uint4*)(smc + bufo + 1 * ARR_B + 16) = rg[3];
        *(uint4*)(smc + bufo + 2 * ARR_B)      = rg[4];
        *(uint4*)(smc + bufo + 2 * ARR_B + 16) = rg[5];
        *(uint4*)(smc + bufo + 3 * ARR_B)      = rg[6];
        *(uint4*)(smc + bufo + 3 * ARR_B + 16) = rg[7];
        __syncthreads();

        if (t + 1 < GKT) {
            const int go = (t + 1) * GBK;
            rg[0] = *(const uint4*)(pAh + go);      rg[1] = *(const uint4*)(pAh + go + 8);
            rg[2] = *(const uint4*)(pAl + go);      rg[3] = *(const uint4*)(pAl + go + 8);
            rg[4] = *(const uint4*)(pBh + go);      rg[5] = *(const uint4*)(pBh + go + 8);
            rg[6] = *(const uint4*)(pBl + go);      rg[7] = *(const uint4*)(pBl + go + 8);
        }

        const uint32_t stg = sb + (uint32_t)((t & 1) * STG_B);
#pragma unroll
        for (int ks = 0; ks < 2; ks++) {
            uint32_t ah[4][4], al[4][4];
#pragma unroll
            for (int mt = 0; mt < 4; mt++) {
                ldsm4(ah[mt], stg + 0 * ARR_B + aoff + mt * 1280 + ks * 32);
                ldsm4(al[mt], stg + 1 * ARR_B + aoff + mt * 1280 + ks * 32);
            }
            uint32_t bh[4][2], bl[4][2];
#pragma unroll
            for (int bt = 0; bt < 2; bt++) {
                uint32_t tmp[4];
                ldsm4(tmp, stg + 2 * ARR_B + boff + bt * 1280 + ks * 32);
                bh[2 * bt][0] = tmp[0]; bh[2 * bt][1] = tmp[1];
                bh[2 * bt + 1][0] = tmp[2]; bh[2 * bt + 1][1] = tmp[3];
                ldsm4(tmp, stg + 3 * ARR_B + boff + bt * 1280 + ks * 32);
                bl[2 * bt][0] = tmp[0]; bl[2 * bt][1] = tmp[1];
                bl[2 * bt + 1][0] = tmp[2]; bl[2 * bt + 1][1] = tmp[3];
            }
#pragma unroll
            for (int mt = 0; mt < 4; mt++)
#pragma unroll
                for (int nt = 0; nt < 4; nt++) {
                    mma16816(acc[mt][nt], ah[mt], bh[nt]);
                    mma16816(acc[mt][nt], ah[mt], bl[nt]);
                    mma16816(acc[mt][nt], al[mt], bh[nt]);
                }
        }
        __syncthreads();
    }

    const int gr = lane >> 2;
    const int gc = (lane & 3) * 2;
#pragma unroll
    for (int mt = 0; mt < 4; mt++) {
        const int row = m0 + wm * 64 + mt * 16 + gr;
#pragma unroll
        for (int nt = 0; nt < 4; nt++) {
            const int col = n0 + wn * 32 + nt * 8 + gc;
            if (SPLIT) {
                store_split2(Ch, Cl, (size_t)row * N + col, acc[mt][nt][0], acc[mt][nt][1]);
                store_split2(Ch, Cl, (size_t)(row + 8) * N + col, acc[mt][nt][2], acc[mt][nt][3]);
            } else {
                *(float2*)&C[(size_t)row * N + col] =
                    make_float2(acc[mt][nt][0], acc[mt][nt][1]);
                *(float2*)&C[(size_t)(row + 8) * N + col] =
                    make_float2(acc[mt][nt][2], acc[mt][nt][3]);
            }
        }
    }
}

// ---------------------------------------------------------------------------
// Flash attention on HMMA (split bf16, fp32 accumulate). Causal.
// Block: 128 threads = 4 warps; Q tile 64 rows (16 rows/warp); KV tiles 64.
// SMEM: 4 arrays of 64 rows x 144 B (Kh|Kl|Vh|Vl; Q staged through 0/1).
// ---------------------------------------------------------------------------
#define FST 144
#define FLASH_SMEM (4 * 64 * FST)   // 36864

__global__ __launch_bounds__(128) void flash_mma(
    const __nv_bfloat16* __restrict__ Qh, const __nv_bfloat16* __restrict__ Ql,
    const __nv_bfloat16* __restrict__ Kh, const __nv_bfloat16* __restrict__ Kl,
    const __nv_bfloat16* __restrict__ Vh, const __nv_bfloat16* __restrict__ Vl,
    __nv_bfloat16* __restrict__ Oh, __nv_bfloat16* __restrict__ Ol) {
    extern __shared__ char smc[];
    const uint32_t sb = smem_to_u32(smc);
    const int tid = threadIdx.x;
    const int w = tid >> 5;
    const int lane = tid & 31;
    const int qt = gridDim.x - 1 - blockIdx.x;   // long blocks first
    const int h = blockIdx.y;
    const int b = blockIdx.z;
    const int q0 = qt * 64;

    const int lrow = tid >> 1;
    const int lh = tid & 1;
    const size_t gbase = (size_t)b * SEQL * D_MODEL + h * HEAD_DIM;

    const int r = lane >> 2;
    const int c2 = (lane & 3) * 2;

    // ldsm lane-address bases
    const uint32_t qaddr = sb + (uint32_t)((w * 16 + (lane & 15)) * FST + (lane >> 4) * 16);
    const uint32_t kaddr = sb + (uint32_t)(((((lane >> 4) << 3) + (lane & 7)) * FST) + ((lane >> 3) & 1) * 16);
    const uint32_t vaddr = sb + (uint32_t)(((((lane >> 3) & 1) * 8 + (lane & 7)) * FST) + (lane >> 4) * 16);

    const uint32_t A0 = 0, A1 = 64 * FST, A2 = 2 * 64 * FST, A3 = 3 * 64 * FST;

    // ---- stage Q tile through buffers 0/1, keep fragments in registers ----
    {
        const size_t rb = gbase + (size_t)(q0 + lrow) * D_MODEL + lh * 32;
        char* d0 = smc + lrow * FST + lh * 64;
#pragma unroll
        for (int j = 0; j < 4; j++) {
            *(uint4*)(d0 + A0 + j * 16) = *(const uint4*)((const char*)(Qh + rb) + j * 16);
            *(uint4*)(d0 + A1 + j * 16) = *(const uint4*)((const char*)(Ql + rb) + j * 16);
        }
    }
    __syncthreads();
    uint32_t qhf[4][4], qlf[4][4];
#pragma unroll
    for (int ks = 0; ks < 4; ks++) {
        ldsm4(qhf[ks], qaddr + A0 + ks * 32);
        ldsm4(qlf[ks], qaddr + A1 + ks * 32);
    }
    __syncthreads();

    float o[8][4];
#pragma unroll
    for (int nt = 0; nt < 8; nt++)
#pragma unroll
        for (int j = 0; j < 4; j++) o[nt][j] = 0.0f;
    float mA = -1e30f, mB = -1e30f, lA = 0.0f, lB = 0.0f;

    for (int kt = 0; kt <= qt; kt++) {
        const int k0 = kt * 64;
        {
            const size_t rb = gbase + (size_t)(k0 + lrow) * D_MODEL + lh * 32;
            char* d0 = smc + lrow * FST + lh * 64;
#pragma unroll
            for (int j = 0; j < 4; j++) {
                *(uint4*)(d0 + A0 + j * 16) = *(const uint4*)((const char*)(Kh + rb) + j * 16);
                *(uint4*)(d0 + A1 + j * 16) = *(const uint4*)((const char*)(Kl + rb) + j * 16);
                *(uint4*)(d0 + A2 + j * 16) = *(const uint4*)((const char*)(Vh + rb) + j * 16);
                *(uint4*)(d0 + A3 + j * 16) = *(const uint4*)((const char*)(Vl + rb) + j * 16);
            }
        }
        __syncthreads();

        // ---- S = Q K^T (split: hh + hl + lh) ----
        float s[8][4];
#pragma unroll
        for (int nt = 0; nt < 8; nt++)
#pragma unroll
            for (int j = 0; j < 4; j++) s[nt][j] = 0.0f;

#pragma unroll
        for (int ks = 0; ks < 4; ks++) {
#pragma unroll
            for (int np = 0; np < 4; np++) {
                uint32_t th[4], tl[4];
                ldsm4(th, kaddr + A0 + np * 16 * FST + ks * 32);
                ldsm4(tl, kaddr + A1 + np * 16 * FST + ks * 32);
                mma16816(s[2 * np],     qhf[ks], th);
                mma16816(s[2 * np + 1], qhf[ks], th + 2);
                mma16816(s[2 * np],     qhf[ks], tl);
                mma16816(s[2 * np + 1], qhf[ks], tl + 2);
                mma16816(s[2 * np],     qlf[ks], th);
                mma16816(s[2 * np + 1], qlf[ks], th + 2);
            }
        }

        // ---- scale + causal mask ----
        const bool diag = (kt == qt);
        const int rowA = w * 16 + r;
        const int rowB = rowA + 8;
#pragma unroll
        for (int nt = 0; nt < 8; nt++)
#pragma unroll
            for (int j = 0; j < 2; j++) {
                const int col = nt * 8 + c2 + j;
                float vA = s[nt][j] * 0.125f;
                float vB = s[nt][j + 2] * 0.125f;
                if (diag && col > rowA) vA = -1e30f;
                if (diag && col > rowB) vB = -1e30f;
                s[nt][j] = vA;
                s[nt][j + 2] = vB;
            }

        // ---- online softmax (rows rowA, rowB per thread; quad reduce) ----
        float mxA = -1e30f, mxB = -1e30f;
#pragma unroll
        for (int nt = 0; nt < 8; nt++) {
            mxA = fmaxf(mxA, fmaxf(s[nt][0], s[nt][1]));
            mxB = fmaxf(mxB, fmaxf(s[nt][2], s[nt][3]));
        }
        mxA = fmaxf(mxA, __shfl_xor_sync(0xffffffffu, mxA, 1));
        mxA = fmaxf(mxA, __shfl_xor_sync(0xffffffffu, mxA, 2));
        mxB = fmaxf(mxB, __shfl_xor_sync(0xffffffffu, mxB, 1));
        mxB = fmaxf(mxB, __shfl_xor_sync(0xffffffffu, mxB, 2));
        const float mnA = fmaxf(mA, mxA);
        const float mnB = fmaxf(mB, mxB);
        float suA = 0.0f, suB = 0.0f;
#pragma unroll
        for (int nt = 0; nt < 8; nt++) {
            float e0 = __expf(s[nt][0] - mnA);
            float e1 = __expf(s[nt][1] - mnA);
            float e2 = __expf(s[nt][2] - mnB);
            float e3 = __expf(s[nt][3] - mnB);
            s[nt][0] = e0; s[nt][1] = e1; s[nt][2] = e2; s[nt][3] = e3;
            suA += e0 + e1;
            suB += e2 + e3;
        }
        suA += __shfl_xor_sync(0xffffffffu, suA, 1);
        suA += __shfl_xor_sync(0xffffffffu, suA, 2);
        suB += __shfl_xor_sync(0xffffffffu, suB, 1);
        suB += __shfl_xor_sync(0xffffffffu, suB, 2);
        const float scA = __expf(mA - mnA);
        const float scB = __expf(mB - mnB);
        mA = mnA; mB = mnB;
        lA = lA * scA + suA;
        lB = lB * scB + suB;
#pragma unroll
        for (int nt = 0; nt < 8; nt++) {
            o[nt][0] *= scA; o[nt][1] *= scA;
            o[nt][2] *= scB; o[nt][3] *= scB;
        }

        // ---- O += P V (P split in-register; V via trans ldmatrix) ----
#pragma unroll
        for (int ks = 0; ks < 4; ks++) {
            uint32_t pha[4], pla[4];
            split2(s[2 * ks][0], s[2 * ks][1], pha[0], pla[0]);
            split2(s[2 * ks][2], s[2 * ks][3], pha[1], pla[1]);
            split2(s[2 * ks + 1][0], s[2 * ks + 1][1], pha[2], pla[2]);
            split2(s[2 * ks + 1][2], s[2 * ks + 1][3], pha[3], pla[3]);
#pragma unroll
            for (int np = 0; np < 4; np++) {
                uint32_t th[4], tl[4];
                ldsm4t(th, vaddr + A2 + ks * 16 * FST + np * 32);
                ldsm4t(tl, vaddr + A3 + ks * 16 * FST + np * 32);
                mma16816(o[2 * np],     pha, th);
                mma16816(o[2 * np + 1], pha, th + 2);
                mma16816(o[2 * np],     pha, tl);
                mma16816(o[2 * np + 1], pha, tl + 2);
                mma16816(o[2 * np],     pla, th);
                mma16816(o[2 * np + 1], pla, th + 2);
            }
        }
        __syncthreads();
    }

    // ---- epilogue: normalize, split-store bf16 hi/lo ----
    const float liA = 1.0f / lA;
    const float liB = 1.0f / lB;
    const size_t orA = gbase + (size_t)(q0 + w * 16 + r) * D_MODEL;
    const size_t orB = orA + (size_t)8 * D_MODEL;
#pragma unroll
    for (int nt = 0; nt < 8; nt++) {
        const int col = nt * 8 + c2;
        store_split2(Oh, Ol, orA + col, o[nt][0] * liA, o[nt][1] * liA);
        store_split2(Oh, Ol, orB + col, o[nt][2] * liB, o[nt][3] * liB);
    }
}

// ---------------------------------------------------------------------------
extern "C" void kernel_launch(void* const* d_in, const int* in_sizes, int n_in,
                              void* d_out, int out_size) {
    const float* x  = (const float*)d_in[0];
    const float* wq = (const float*)d_in[1];
    const float* wk = (const float*)d_in[2];
    const float* wv = (const float*)d_in[3];
    const float* wo = (const float*)d_in[4];
    float* out = (float*)d_out;

    __nv_bfloat16 *xh, *xl, *qh, *ql, *kh, *kl, *vh, *vl, *ath, *atl;
    __nv_bfloat16 *wqh, *wql, *wkh, *wkl, *wvh, *wvl, *woh, *wol;
    cudaGetSymbolAddress((void**)&xh, g_xh);   cudaGetSymbolAddress((void**)&xl, g_xl);
    cudaGetSymbolAddress((void**)&qh, g_qh);   cudaGetSymbolAddress((void**)&ql, g_ql);
    cudaGetSymbolAddress((void**)&kh, g_kh);   cudaGetSymbolAddress((void**)&kl, g_kl);
    cudaGetSymbolAddress((void**)&vh, g_vh);   cudaGetSymbolAddress((void**)&vl, g_vl);
    cudaGetSymbolAddress((void**)&ath, g_ath); cudaGetSymbolAddress((void**)&atl, g_atl);
    cudaGetSymbolAddress((void**)&wqh, g_wqh); cudaGetSymbolAddress((void**)&wql, g_wql);
    cudaGetSymbolAddress((void**)&wkh, g_wkh); cudaGetSymbolAddress((void**)&wkl, g_wkl);
    cudaGetSymbolAddress((void**)&wvh, g_wvh); cudaGetSymbolAddress((void**)&wvl, g_wvl);
    cudaGetSymbolAddress((void**)&woh, g_woh); cudaGetSymbolAddress((void**)&wol, g_wol);

    cudaFuncSetAttribute(gemm_mma_nt<true>,  cudaFuncAttributeMaxDynamicSharedMemorySize, GEMM_SMEM);
    cudaFuncSetAttribute(gemm_mma_nt<false>, cudaFuncAttributeMaxDynamicSharedMemorySize, GEMM_SMEM);
    cudaFuncSetAttribute(flash_mma, cudaFuncAttributeMaxDynamicSharedMemorySize, FLASH_SMEM);

    const int nx4 = MROWS * D_MODEL / 4;
    const int nw4 = D_MODEL * D_MODEL / 4;

    split_bf16_k<<<(nx4 + 255) / 256, 256>>>((const float4*)x, (__nv_bfloat162*)xh, (__nv_bfloat162*)xl, nx4);
    split_bf16_k<<<(nw4 + 255) / 256, 256>>>((const float4*)wq, (__nv_bfloat162*)wqh, (__nv_bfloat162*)wql, nw4);
    split_bf16_k<<<(nw4 + 255) / 256, 256>>>((const float4*)wk, (__nv_bfloat162*)wkh, (__nv_bfloat162*)wkl, nw4);
    split_bf16_k<<<(nw4 + 255) / 256, 256>>>((const float4*)wv, (__nv_bfloat162*)wvh, (__nv_bfloat162*)wvl, nw4);
    split_bf16_k<<<(nw4 + 255) / 256, 256>>>((const float4*)wo, (__nv_bfloat162*)woh, (__nv_bfloat162*)wol, nw4);

    dim3 gg(D_MODEL / 128, MROWS / 128);   // (8, 32)
    gemm_mma_nt<true><<<gg, 256, GEMM_SMEM>>>(xh, xl, wqh, wql, nullptr, qh, ql, MROWS, D_MODEL, D_MODEL);
    gemm_mma_nt<true><<<gg, 256, GEMM_SMEM>>>(xh, xl, wkh, wkl, nullptr, kh, kl, MROWS, D_MODEL, D_MODEL);
    gemm_mma_nt<true><<<gg, 256, GEMM_SMEM>>>(xh, xl, wvh, wvl, nullptr, vh, vl, MROWS, D_MODEL, D_MODEL);

    flash_mma<<<dim3(SEQL / 64, N_HEADS, BATCH), 128, FLASH_SMEM>>>(qh, ql, kh, kl, vh, vl, ath, atl);

    gemm_mma_nt<false><<<gg, 256, GEMM_SMEM>>>(ath, atl, woh, wol, out, nullptr, nullptr, MROWS, D_MODEL, D_MODEL);
}

// round 6
// speedup vs baseline: 3.2713x; 1.2642x over previous
#include <cuda_runtime.h>
#include <cuda_fp16.h>
#include <cstdint>
#include <math.h>

#define D_MODEL 1024
#define N_HEADS 16
#define HEAD_DIM 64
#define BATCH 2
#define SEQL 2048
#define MROWS (BATCH * SEQL)   // 4096

// ---------------- scratch (device globals: allocation-free rule) -----------
__device__ __half g_xh[MROWS * D_MODEL];
__device__ __half g_qh[MROWS * D_MODEL];
__device__ __half g_kh[MROWS * D_MODEL];
__device__ __half g_kl[MROWS * D_MODEL];
__device__ __half g_vh[MROWS * D_MODEL];
__device__ __half g_vl[MROWS * D_MODEL];
__device__ __half g_ath[MROWS * D_MODEL];
__device__ __half g_wqh[D_MODEL * D_MODEL];
__device__ __half g_wql[D_MODEL * D_MODEL];
__device__ __half g_wkh[D_MODEL * D_MODEL];
__device__ __half g_wkl[D_MODEL * D_MODEL];
__device__ __half g_wvh[D_MODEL * D_MODEL];
__device__ __half g_wvl[D_MODEL * D_MODEL];
__device__ __half g_woh[D_MODEL * D_MODEL];
__device__ __half g_wol[D_MODEL * D_MODEL];

// ---------------- helpers ---------------------------------------------------
__device__ __forceinline__ uint32_t smem_to_u32(const void* p) {
    uint32_t a;
    asm("{ .reg .u64 t; cvta.to.shared.u64 t, %1; cvt.u32.u64 %0, t; }" : "=r"(a) : "l"(p));
    return a;
}

__device__ __forceinline__ void ldsm4(uint32_t* r, uint32_t addr) {
    asm volatile("ldmatrix.sync.aligned.m8n8.x4.shared.b16 {%0,%1,%2,%3}, [%4];"
                 : "=r"(r[0]), "=r"(r[1]), "=r"(r[2]), "=r"(r[3]) : "r"(addr));
}

__device__ __forceinline__ void ldsm4t(uint32_t* r, uint32_t addr) {
    asm volatile("ldmatrix.sync.aligned.m8n8.x4.trans.shared.b16 {%0,%1,%2,%3}, [%4];"
                 : "=r"(r[0]), "=r"(r[1]), "=r"(r[2]), "=r"(r[3]) : "r"(addr));
}

__device__ __forceinline__ void mma16816(float* d, const uint32_t* a, const uint32_t* b) {
    asm volatile(
        "mma.sync.aligned.m16n8k16.row.col.f32.f16.f16.f32 "
        "{%0,%1,%2,%3}, {%4,%5,%6,%7}, {%8,%9}, {%0,%1,%2,%3};"
        : "+f"(d[0]), "+f"(d[1]), "+f"(d[2]), "+f"(d[3])
        : "r"(a[0]), "r"(a[1]), "r"(a[2]), "r"(a[3]), "r"(b[0]), "r"(b[1]));
}

__device__ __forceinline__ uint32_t packh2(float x, float y) {
    __half2 h = __floats2half2_rn(x, y);
    return *(uint32_t*)&h;
}

// split (x,y) fp32 -> packed fp16x2 hi + packed fp16x2 lo
__device__ __forceinline__ void split2h(float x, float y, uint32_t& hi, uint32_t& lo) {
    __half2 h = __floats2half2_rn(x, y);
    float2 hf = __half22float2(h);
    __half2 l = __floats2half2_rn(x - hf.x, y - hf.y);
    hi = *(uint32_t*)&h;
    lo = *(uint32_t*)&l;
}

// ---------------------------------------------------------------------------
// convert fp32 -> fp16 hi only
// ---------------------------------------------------------------------------
__global__ __launch_bounds__(256) void cvt_h_k(const float4* __restrict__ in,
                                               uint32_t* __restrict__ hi, int n4) {
    int i = blockIdx.x * blockDim.x + threadIdx.x;
    if (i >= n4) return;
    float4 v = in[i];
    hi[2 * i]     = packh2(v.x, v.y);
    hi[2 * i + 1] = packh2(v.z, v.w);
}

// split fp32 -> (fp16 hi, fp16 lo)
__global__ __launch_bounds__(256) void split_h_k(const float4* __restrict__ in,
                                                 uint32_t* __restrict__ hi,
                                                 uint32_t* __restrict__ lo, int n4) {
    int i = blockIdx.x * blockDim.x + threadIdx.x;
    if (i >= n4) return;
    float4 v = in[i];
    uint32_t h0, l0, h1, l1;
    split2h(v.x, v.y, h0, l0);
    split2h(v.z, v.w, h1, l1);
    hi[2 * i] = h0; hi[2 * i + 1] = h1;
    lo[2 * i] = l0; lo[2 * i + 1] = l1;
}

// ---------------------------------------------------------------------------
// HMMA fp16 2-pass GEMM-NT: C[m,n] = sum_k A[m,k]*B[n,k]
// A given as fp16-hi only; B as (Bh, Bl). C = Ah*Bh + Ah*Bl.
// CTA 128x128, BK=32. 8 warps (2x4), warp tile 64x32 via m16n8k16.
// OUT: 0 = fp32 C, 1 = fp16 hi only (Ch), 2 = fp16 hi+lo (Ch, Cl)
// ---------------------------------------------------------------------------
#define GBK 32
#define GKT (D_MODEL / GBK)          // 32
#define ARR_B 10240                  // 128 rows * 80 B
#define STG_B (3 * ARR_B)            // Ah | Bh | Bl = 30720
#define GEMM_SMEM (2 * STG_B)        // 61440

template <int OUT>
__global__ __launch_bounds__(256, 1) void gemm_mma_nt(
    const __half* __restrict__ Ah,
    const __half* __restrict__ Bh, const __half* __restrict__ Bl,
    float* __restrict__ C, __half* __restrict__ Ch, __half* __restrict__ Cl,
    int M, int N, int K) {
    extern __shared__ char smc[];
    const uint32_t sb = smem_to_u32(smc);

    const int tid = threadIdx.x;
    const int wid = tid >> 5;
    const int lane = tid & 31;
    const int wm = wid >> 2;
    const int wn = wid & 3;
    const int m0 = blockIdx.y * 128;
    const int n0 = blockIdx.x * 128;

    const int lrow = tid >> 1;
    const int lhof = (tid & 1) * 16;
    const __half* pAh = Ah + (size_t)(m0 + lrow) * K + lhof;
    const __half* pBh = Bh + (size_t)(n0 + lrow) * K + lhof;
    const __half* pBl = Bl + (size_t)(n0 + lrow) * K + lhof;
    const uint32_t sdst = lrow * 80 + (tid & 1) * 32;

    const uint32_t aoff = (uint32_t)((wm * 64 + (lane & 15)) * 80 + (lane >> 4) * 16);
    const int j8 = lane >> 3;
    const uint32_t boff = (uint32_t)((wn * 32 + ((j8 >> 1) << 3) + (lane & 7)) * 80 + (j8 & 1) * 16);

    float acc[4][4][4];
#pragma unroll
    for (int a = 0; a < 4; a++)
#pragma unroll
        for (int b = 0; b < 4; b++)
#pragma unroll
            for (int c = 0; c < 4; c++) acc[a][b][c] = 0.0f;

    uint4 rg[6];
    rg[0] = *(const uint4*)(pAh);      rg[1] = *(const uint4*)(pAh + 8);
    rg[2] = *(const uint4*)(pBh);      rg[3] = *(const uint4*)(pBh + 8);
    rg[4] = *(const uint4*)(pBl);      rg[5] = *(const uint4*)(pBl + 8);

    for (int t = 0; t < GKT; t++) {
        const uint32_t bufo = (uint32_t)((t & 1) * STG_B) + sdst;
        *(uint4*)(smc + bufo + 0 * ARR_B)      = rg[0];
        *(uint4*)(smc + bufo + 0 * ARR_B + 16) = rg[1];
        *(uint4*)(smc + bufo + 1 * ARR_B)      = rg[2];
        *(uint4*)(smc + bufo + 1 * ARR_B + 16) = rg[3];
        *(uint4*)(smc + bufo + 2 * ARR_B)      = rg[4];
        *(uint4*)(smc + bufo + 2 * ARR_B + 16) = rg[5];
        __syncthreads();

        if (t + 1 < GKT) {
            const int go = (t + 1) * GBK;
            rg[0] = *(const uint4*)(pAh + go);      rg[1] = *(const uint4*)(pAh + go + 8);
            rg[2] = *(const uint4*)(pBh + go);      rg[3] = *(const uint4*)(pBh + go + 8);
            rg[4] = *(const uint4*)(pBl + go);      rg[5] = *(const uint4*)(pBl + go + 8);
        }

        const uint32_t stg = sb + (uint32_t)((t & 1) * STG_B);
#pragma unroll
        for (int ks = 0; ks < 2; ks++) {
            uint32_t ah[4][4];
#pragma unroll
            for (int mt = 0; mt < 4; mt++)
                ldsm4(ah[mt], stg + 0 * ARR_B + aoff + mt * 1280 + ks * 32);
            uint32_t bh[4][2], bl[4][2];
#pragma unroll
            for (int bt = 0; bt < 2; bt++) {
                uint32_t tmp[4];
                ldsm4(tmp, stg + 1 * ARR_B + boff + bt * 1280 + ks * 32);
                bh[2 * bt][0] = tmp[0]; bh[2 * bt][1] = tmp[1];
                bh[2 * bt + 1][0] = tmp[2]; bh[2 * bt + 1][1] = tmp[3];
                ldsm4(tmp, stg + 2 * ARR_B + boff + bt * 1280 + ks * 32);
                bl[2 * bt][0] = tmp[0]; bl[2 * bt][1] = tmp[1];
                bl[2 * bt + 1][0] = tmp[2]; bl[2 * bt + 1][1] = tmp[3];
            }
#pragma unroll
            for (int mt = 0; mt < 4; mt++)
#pragma unroll
                for (int nt = 0; nt < 4; nt++) {
                    mma16816(acc[mt][nt], ah[mt], bh[nt]);
                    mma16816(acc[mt][nt], ah[mt], bl[nt]);
                }
        }
        __syncthreads();
    }

    const int gr = lane >> 2;
    const int gc = (lane & 3) * 2;
#pragma unroll
    for (int mt = 0; mt < 4; mt++) {
        const int row = m0 + wm * 64 + mt * 16 + gr;
#pragma unroll
        for (int nt = 0; nt < 4; nt++) {
            const int col = n0 + wn * 32 + nt * 8 + gc;
            const size_t i0 = (size_t)row * N + col;
            const size_t i1 = (size_t)(row + 8) * N + col;
            if (OUT == 0) {
                *(float2*)&C[i0] = make_float2(acc[mt][nt][0], acc[mt][nt][1]);
                *(float2*)&C[i1] = make_float2(acc[mt][nt][2], acc[mt][nt][3]);
            } else if (OUT == 1) {
                *(uint32_t*)(Ch + i0) = packh2(acc[mt][nt][0], acc[mt][nt][1]);
                *(uint32_t*)(Ch + i1) = packh2(acc[mt][nt][2], acc[mt][nt][3]);
            } else {
                uint32_t hi, lo;
                split2h(acc[mt][nt][0], acc[mt][nt][1], hi, lo);
                *(uint32_t*)(Ch + i0) = hi;
                *(uint32_t*)(Cl + i0) = lo;
                split2h(acc[mt][nt][2], acc[mt][nt][3], hi, lo);
                *(uint32_t*)(Ch + i1) = hi;
                *(uint32_t*)(Cl + i1) = lo;
            }
        }
    }
}

// ---------------------------------------------------------------------------
// Flash attention on HMMA, fp16 2-pass (Q hi-only; K,V split). Causal.
// Block: 128 threads = 4 warps; Q tile 64 rows; KV tiles 64.
// SMEM: 4 arrays of 64 rows x 144 B (Kh|Kl|Vh|Vl; Q staged through 0).
// ---------------------------------------------------------------------------
#define FST 144
#define FLASH_SMEM (4 * 64 * FST)   // 36864

__global__ __launch_bounds__(128) void flash_mma(
    const __half* __restrict__ Qh,
    const __half* __restrict__ Kh, const __half* __restrict__ Kl,
    const __half* __restrict__ Vh, const __half* __restrict__ Vl,
    __half* __restrict__ Oh) {
    extern __shared__ char smc[];
    const uint32_t sb = smem_to_u32(smc);
    const int tid = threadIdx.x;
    const int w = tid >> 5;
    const int lane = tid & 31;
    const int qt = gridDim.x - 1 - blockIdx.x;   // long blocks first
    const int h = blockIdx.y;
    const int b = blockIdx.z;
    const int q0 = qt * 64;

    const int lrow = tid >> 1;
    const int lh = tid & 1;
    const size_t gbase = (size_t)b * SEQL * D_MODEL + h * HEAD_DIM;

    const int r = lane >> 2;
    const int c2 = (lane & 3) * 2;

    const uint32_t qaddr = sb + (uint32_t)((w * 16 + (lane & 15)) * FST + (lane >> 4) * 16);
    const uint32_t kaddr = sb + (uint32_t)(((((lane >> 4) << 3) + (lane & 7)) * FST) + ((lane >> 3) & 1) * 16);
    const uint32_t vaddr = sb + (uint32_t)(((((lane >> 3) & 1) * 8 + (lane & 7)) * FST) + (lane >> 4) * 16);

    const uint32_t A0 = 0, A1 = 64 * FST, A2 = 2 * 64 * FST, A3 = 3 * 64 * FST;

    // ---- stage Q tile through buffer 0, keep fragments in registers ----
    {
        const size_t rb = gbase + (size_t)(q0 + lrow) * D_MODEL + lh * 32;
        char* d0 = smc + lrow * FST + lh * 64;
#pragma unroll
        for (int j = 0; j < 4; j++)
            *(uint4*)(d0 + A0 + j * 16) = *(const uint4*)((const char*)(Qh + rb) + j * 16);
    }
    __syncthreads();
    uint32_t qhf[4][4];
#pragma unroll
    for (int ks = 0; ks < 4; ks++)
        ldsm4(qhf[ks], qaddr + A0 + ks * 32);
    __syncthreads();

    float o[8][4];
#pragma unroll
    for (int nt = 0; nt < 8; nt++)
#pragma unroll
        for (int j = 0; j < 4; j++) o[nt][j] = 0.0f;
    float mA = -1e30f, mB = -1e30f, lA = 0.0f, lB = 0.0f;

    for (int kt = 0; kt <= qt; kt++) {
        const int k0 = kt * 64;
        {
            const size_t rb = gbase + (size_t)(k0 + lrow) * D_MODEL + lh * 32;
            char* d0 = smc + lrow * FST + lh * 64;
#pragma unroll
            for (int j = 0; j < 4; j++) {
                *(uint4*)(d0 + A0 + j * 16) = *(const uint4*)((const char*)(Kh + rb) + j * 16);
                *(uint4*)(d0 + A1 + j * 16) = *(const uint4*)((const char*)(Kl + rb) + j * 16);
                *(uint4*)(d0 + A2 + j * 16) = *(const uint4*)((const char*)(Vh + rb) + j * 16);
                *(uint4*)(d0 + A3 + j * 16) = *(const uint4*)((const char*)(Vl + rb) + j * 16);
            }
        }
        __syncthreads();

        // ---- S = Qh (Kh + Kl)^T ----
        float s[8][4];
#pragma unroll
        for (int nt = 0; nt < 8; nt++)
#pragma unroll
            for (int j = 0; j < 4; j++) s[nt][j] = 0.0f;

#pragma unroll
        for (int ks = 0; ks < 4; ks++) {
#pragma unroll
            for (int np = 0; np < 4; np++) {
                uint32_t th[4], tl[4];
                ldsm4(th, kaddr + A0 + np * 16 * FST + ks * 32);
                ldsm4(tl, kaddr + A1 + np * 16 * FST + ks * 32);
                mma16816(s[2 * np],     qhf[ks], th);
                mma16816(s[2 * np + 1], qhf[ks], th + 2);
                mma16816(s[2 * np],     qhf[ks], tl);
                mma16816(s[2 * np + 1], qhf[ks], tl + 2);
            }
        }

        // ---- scale + causal mask ----
        const bool diag = (kt == qt);
        const int rowA = w * 16 + r;
        const int rowB = rowA + 8;
#pragma unroll
        for (int nt = 0; nt < 8; nt++)
#pragma unroll
            for (int j = 0; j < 2; j++) {
                const int col = nt * 8 + c2 + j;
                float vA = s[nt][j] * 0.125f;
                float vB = s[nt][j + 2] * 0.125f;
                if (diag && col > rowA) vA = -1e30f;
                if (diag && col > rowB) vB = -1e30f;
                s[nt][j] = vA;
                s[nt][j + 2] = vB;
            }

        // ---- online softmax ----
        float mxA = -1e30f, mxB = -1e30f;
#pragma unroll
        for (int nt = 0; nt < 8; nt++) {
            mxA = fmaxf(mxA, fmaxf(s[nt][0], s[nt][1]));
            mxB = fmaxf(mxB, fmaxf(s[nt][2], s[nt][3]));
        }
        mxA = fmaxf(mxA, __shfl_xor_sync(0xffffffffu, mxA, 1));
        mxA = fmaxf(mxA, __shfl_xor_sync(0xffffffffu, mxA, 2));
        mxB = fmaxf(mxB, __shfl_xor_sync(0xffffffffu, mxB, 1));
        mxB = fmaxf(mxB, __shfl_xor_sync(0xffffffffu, mxB, 2));
        const float mnA = fmaxf(mA, mxA);
        const float mnB = fmaxf(mB, mxB);
        float suA = 0.0f, suB = 0.0f;
#pragma unroll
        for (int nt = 0; nt < 8; nt++) {
            float e0 = __expf(s[nt][0] - mnA);
            float e1 = __expf(s[nt][1] - mnA);
            float e2 = __expf(s[nt][2] - mnB);
            float e3 = __expf(s[nt][3] - mnB);
            s[nt][0] = e0; s[nt][1] = e1; s[nt][2] = e2; s[nt][3] = e3;
            suA += e0 + e1;
            suB += e2 + e3;
        }
        suA += __shfl_xor_sync(0xffffffffu, suA, 1);
        suA += __shfl_xor_sync(0xffffffffu, suA, 2);
        suB += __shfl_xor_sync(0xffffffffu, suB, 1);
        suB += __shfl_xor_sync(0xffffffffu, suB, 2);
        const float scA = __expf(mA - mnA);
        const float scB = __expf(mB - mnB);
        mA = mnA; mB = mnB;
        lA = lA * scA + suA;
        lB = lB * scB + suB;
#pragma unroll
        for (int nt = 0; nt < 8; nt++) {
            o[nt][0] *= scA; o[nt][1] *= scA;
            o[nt][2] *= scB; o[nt][3] *= scB;
        }

        // ---- O += Ph (Vh + Vl) ----
#pragma unroll
        for (int ks = 0; ks < 4; ks++) {
            uint32_t pha[4];
            pha[0] = packh2(s[2 * ks][0], s[2 * ks][1]);
            pha[1] = packh2(s[2 * ks][2], s[2 * ks][3]);
            pha[2] = packh2(s[2 * ks + 1][0], s[2 * ks + 1][1]);
            pha[3] = packh2(s[2 * ks + 1][2], s[2 * ks + 1][3]);
#pragma unroll
            for (int np = 0; np < 4; np++) {
                uint32_t th[4], tl[4];
                ldsm4t(th, vaddr + A2 + ks * 16 * FST + np * 32);
                ldsm4t(tl, vaddr + A3 + ks * 16 * FST + np * 32);
                mma16816(o[2 * np],     pha, th);
                mma16816(o[2 * np + 1], pha, th + 2);
                mma16816(o[2 * np],     pha, tl);
                mma16816(o[2 * np + 1], pha, tl + 2);
            }
        }
        __syncthreads();
    }

    // ---- epilogue: normalize, store fp16 hi ----
    const float liA = 1.0f / lA;
    const float liB = 1.0f / lB;
    const size_t orA = gbase + (size_t)(q0 + w * 16 + r) * D_MODEL;
    const size_t orB = orA + (size_t)8 * D_MODEL;
#pragma unroll
    for (int nt = 0; nt < 8; nt++) {
        const int col = nt * 8 + c2;
        *(uint32_t*)(Oh + orA + col) = packh2(o[nt][0] * liA, o[nt][1] * liA);
        *(uint32_t*)(Oh + orB + col) = packh2(o[nt][2] * liB, o[nt][3] * liB);
    }
}

// ---------------------------------------------------------------------------
extern "C" void kernel_launch(void* const* d_in, const int* in_sizes, int n_in,
                              void* d_out, int out_size) {
    const float* x  = (const float*)d_in[0];
    const float* wq = (const float*)d_in[1];
    const float* wk = (const float*)d_in[2];
    const float* wv = (const float*)d_in[3];
    const float* wo = (const float*)d_in[4];
    float* out = (float*)d_out;

    __half *xh, *qh, *kh, *kl, *vh, *vl, *ath;
    __half *wqh, *wql, *wkh, *wkl, *wvh, *wvl, *woh, *wol;
    cudaGetSymbolAddress((void**)&xh, g_xh);
    cudaGetSymbolAddress((void**)&qh, g_qh);
    cudaGetSymbolAddress((void**)&kh, g_kh);   cudaGetSymbolAddress((void**)&kl, g_kl);
    cudaGetSymbolAddress((void**)&vh, g_vh);   cudaGetSymbolAddress((void**)&vl, g_vl);
    cudaGetSymbolAddress((void**)&ath, g_ath);
    cudaGetSymbolAddress((void**)&wqh, g_wqh); cudaGetSymbolAddress((void**)&wql, g_wql);
    cudaGetSymbolAddress((void**)&wkh, g_wkh); cudaGetSymbolAddress((void**)&wkl, g_wkl);
    cudaGetSymbolAddress((void**)&wvh, g_wvh); cudaGetSymbolAddress((void**)&wvl, g_wvl);
    cudaGetSymbolAddress((void**)&woh, g_woh); cudaGetSymbolAddress((void**)&wol, g_wol);

    cudaFuncSetAttribute(gemm_mma_nt<0>, cudaFuncAttributeMaxDynamicSharedMemorySize, GEMM_SMEM);
    cudaFuncSetAttribute(gemm_mma_nt<1>, cudaFuncAttributeMaxDynamicSharedMemorySize, GEMM_SMEM);
    cudaFuncSetAttribute(gemm_mma_nt<2>, cudaFuncAttributeMaxDynamicSharedMemorySize, GEMM_SMEM);
    cudaFuncSetAttribute(flash_mma, cudaFuncAttributeMaxDynamicSharedMemorySize, FLASH_SMEM);

    const int nx4 = MROWS * D_MODEL / 4;
    const int nw4 = D_MODEL * D_MODEL / 4;

    cvt_h_k<<<(nx4 + 255) / 256, 256>>>((const float4*)x, (uint32_t*)xh, nx4);
    split_h_k<<<(nw4 + 255) / 256, 256>>>((const float4*)wq, (uint32_t*)wqh, (uint32_t*)wql, nw4);
    split_h_k<<<(nw4 + 255) / 256, 256>>>((const float4*)wk, (uint32_t*)wkh, (uint32_t*)wkl, nw4);
    split_h_k<<<(nw4 + 255) / 256, 256>>>((const float4*)wv, (uint32_t*)wvh, (uint32_t*)wvl, nw4);
    split_h_k<<<(nw4 + 255) / 256, 256>>>((const float4*)wo, (uint32_t*)woh, (uint32_t*)wol, nw4);

    dim3 gg(D_MODEL / 128, MROWS / 128);   // (8, 32)
    gemm_mma_nt<1><<<gg, 256, GEMM_SMEM>>>(xh, wqh, wql, nullptr, qh, nullptr, MROWS, D_MODEL, D_MODEL);
    gemm_mma_nt<2><<<gg, 256, GEMM_SMEM>>>(xh, wkh, wkl, nullptr, kh, kl, MROWS, D_MODEL, D_MODEL);
    gemm_mma_nt<2><<<gg, 256, GEMM_SMEM>>>(xh, wvh, wvl, nullptr, vh, vl, MROWS, D_MODEL, D_MODEL);

    flash_mma<<<dim3(SEQL / 64, N_HEADS, BATCH), 128, FLASH_SMEM>>>(qh, kh, kl, vh, vl, ath);

    gemm_mma_nt<0><<<gg, 256, GEMM_SMEM>>>(ath, woh, wol, out, nullptr, nullptr, MROWS, D_MODEL, D_MODEL);
}

// round 7
// speedup vs baseline: 3.6337x; 1.1108x over previous
#include <cuda_runtime.h>
#include <cuda_fp16.h>
#include <cstdint>
#include <math.h>

#define D_MODEL 1024
#define N_HEADS 16
#define HEAD_DIM 64
#define BATCH 2
#define SEQL 2048
#define MROWS (BATCH * SEQL)   // 4096

// ---------------- scratch (device globals: allocation-free rule) -----------
__device__ __half g_xh[MROWS * D_MODEL];
__device__ __half g_qh[MROWS * D_MODEL];
__device__ __half g_ql[MROWS * D_MODEL];
__device__ __half g_kh[MROWS * D_MODEL];
__device__ __half g_kl[MROWS * D_MODEL];
__device__ __half g_vh[MROWS * D_MODEL];
__device__ __half g_vl[MROWS * D_MODEL];
__device__ __half g_ath[MROWS * D_MODEL];
__device__ __half g_wqh[D_MODEL * D_MODEL];
__device__ __half g_wql[D_MODEL * D_MODEL];
__device__ __half g_wkh[D_MODEL * D_MODEL];
__device__ __half g_wkl[D_MODEL * D_MODEL];
__device__ __half g_wvh[D_MODEL * D_MODEL];
__device__ __half g_wvl[D_MODEL * D_MODEL];
__device__ __half g_woh[D_MODEL * D_MODEL];
__device__ __half g_wol[D_MODEL * D_MODEL];

// ---------------- helpers ---------------------------------------------------
__device__ __forceinline__ uint32_t smem_to_u32(const void* p) {
    uint32_t a;
    asm("{ .reg .u64 t; cvta.to.shared.u64 t, %1; cvt.u32.u64 %0, t; }" : "=r"(a) : "l"(p));
    return a;
}

#define CPA16(dst, src) \
    asm volatile("cp.async.cg.shared.global [%0], [%1], 16;" :: "r"(dst), "l"(src) : "memory")
#define CPCOMMIT() asm volatile("cp.async.commit_group;" ::: "memory")
#define CPWAIT0() asm volatile("cp.async.wait_group 0;" ::: "memory")
#define CPWAIT1() asm volatile("cp.async.wait_group 1;" ::: "memory")

__device__ __forceinline__ void ldsm4(uint32_t* r, uint32_t addr) {
    asm volatile("ldmatrix.sync.aligned.m8n8.x4.shared.b16 {%0,%1,%2,%3}, [%4];"
                 : "=r"(r[0]), "=r"(r[1]), "=r"(r[2]), "=r"(r[3]) : "r"(addr));
}

__device__ __forceinline__ void ldsm4t(uint32_t* r, uint32_t addr) {
    asm volatile("ldmatrix.sync.aligned.m8n8.x4.trans.shared.b16 {%0,%1,%2,%3}, [%4];"
                 : "=r"(r[0]), "=r"(r[1]), "=r"(r[2]), "=r"(r[3]) : "r"(addr));
}

__device__ __forceinline__ void mma16816(float* d, const uint32_t* a, const uint32_t* b) {
    asm volatile(
        "mma.sync.aligned.m16n8k16.row.col.f32.f16.f16.f32 "
        "{%0,%1,%2,%3}, {%4,%5,%6,%7}, {%8,%9}, {%0,%1,%2,%3};"
        : "+f"(d[0]), "+f"(d[1]), "+f"(d[2]), "+f"(d[3])
        : "r"(a[0]), "r"(a[1]), "r"(a[2]), "r"(a[3]), "r"(b[0]), "r"(b[1]));
}

__device__ __forceinline__ uint32_t packh2(float x, float y) {
    __half2 h = __floats2half2_rn(x, y);
    return *(uint32_t*)&h;
}

__device__ __forceinline__ void split2h(float x, float y, uint32_t& hi, uint32_t& lo) {
    __half2 h = __floats2half2_rn(x, y);
    float2 hf = __half22float2(h);
    __half2 l = __floats2half2_rn(x - hf.x, y - hf.y);
    hi = *(uint32_t*)&h;
    lo = *(uint32_t*)&l;
}

// ---------------------------------------------------------------------------
// converts / splits
// ---------------------------------------------------------------------------
__global__ __launch_bounds__(256) void cvt_h_k(const float4* __restrict__ in,
                                               uint32_t* __restrict__ hi, int n4) {
    int i = blockIdx.x * blockDim.x + threadIdx.x;
    if (i >= n4) return;
    float4 v = in[i];
    hi[2 * i]     = packh2(v.x, v.y);
    hi[2 * i + 1] = packh2(v.z, v.w);
}

__global__ __launch_bounds__(256) void split4_h_k(
    const float4* __restrict__ w0, const float4* __restrict__ w1,
    const float4* __restrict__ w2, const float4* __restrict__ w3,
    uint32_t* __restrict__ h0, uint32_t* __restrict__ l0,
    uint32_t* __restrict__ h1, uint32_t* __restrict__ l1,
    uint32_t* __restrict__ h2, uint32_t* __restrict__ l2,
    uint32_t* __restrict__ h3, uint32_t* __restrict__ l3, int n4) {
    int i = blockIdx.x * blockDim.x + threadIdx.x;
    if (i >= n4) return;
    const float4* in; uint32_t* hi; uint32_t* lo;
    switch (blockIdx.y) {
        case 0:  in = w0; hi = h0; lo = l0; break;
        case 1:  in = w1; hi = h1; lo = l1; break;
        case 2:  in = w2; hi = h2; lo = l2; break;
        default: in = w3; hi = h3; lo = l3; break;
    }
    float4 v = in[i];
    uint32_t a0, b0, a1, b1;
    split2h(v.x, v.y, a0, b0);
    split2h(v.z, v.w, a1, b1);
    hi[2 * i] = a0; hi[2 * i + 1] = a1;
    lo[2 * i] = b0; lo[2 * i + 1] = b1;
}

// ---------------------------------------------------------------------------
// HMMA fp16 2-pass GEMM-NT body: C[m,n] = sum_k A[m,k]*(Bh+Bl)[n,k]
// CTA 128x128, BK=32, cp.async double-buffered, 2 CTAs/SM.
// ---------------------------------------------------------------------------
#define GBK 32
#define GKT (D_MODEL / GBK)          // 32
#define ARR_B 10240                  // 128 rows * 80 B
#define STG_B (3 * ARR_B)            // Ah | Bh | Bl = 30720
#define GEMM_SMEM (2 * STG_B)        // 61440

template <int OUT>   // 0 = fp32 C, 2 = fp16 split (Ch, Cl)
__device__ __forceinline__ void gemm_body(
    char* smc, const __half* __restrict__ Ah,
    const __half* __restrict__ Bh, const __half* __restrict__ Bl,
    float* __restrict__ C, __half* __restrict__ Ch, __half* __restrict__ Cl,
    int m0, int n0) {
    const uint32_t sb = smem_to_u32(smc);
    const int tid = threadIdx.x;
    const int wid = tid >> 5;
    const int lane = tid & 31;
    const int wm = wid >> 2;
    const int wn = wid & 3;

    const int lrow = tid >> 1;
    const int lhof = (tid & 1) * 16;
    const __half* pA  = Ah + (size_t)(m0 + lrow) * D_MODEL + lhof;
    const __half* pB1 = Bh + (size_t)(n0 + lrow) * D_MODEL + lhof;
    const __half* pB2 = Bl + (size_t)(n0 + lrow) * D_MODEL + lhof;
    const uint32_t sdst = (uint32_t)(lrow * 80 + (tid & 1) * 32);

    const uint32_t aoff = (uint32_t)((wm * 64 + (lane & 15)) * 80 + (lane >> 4) * 16);
    const int j8 = lane >> 3;
    const uint32_t boff = (uint32_t)((wn * 32 + ((j8 >> 1) << 3) + (lane & 7)) * 80 + (j8 & 1) * 16);

    float acc[4][4][4];
#pragma unroll
    for (int a = 0; a < 4; a++)
#pragma unroll
        for (int b = 0; b < 4; b++)
#pragma unroll
            for (int c = 0; c < 4; c++) acc[a][b][c] = 0.0f;

#define G_ISSUE(s) do {                                                       \
        const uint32_t d = sb + (uint32_t)(((s) & 1) * STG_B) + sdst;         \
        const int go = (s) * GBK;                                             \
        CPA16(d + 0 * ARR_B,      pA  + go);                                  \
        CPA16(d + 0 * ARR_B + 16, pA  + go + 8);                              \
        CPA16(d + 1 * ARR_B,      pB1 + go);                                  \
        CPA16(d + 1 * ARR_B + 16, pB1 + go + 8);                              \
        CPA16(d + 2 * ARR_B,      pB2 + go);                                  \
        CPA16(d + 2 * ARR_B + 16, pB2 + go + 8);                              \
    } while (0)

    G_ISSUE(0); CPCOMMIT();
    G_ISSUE(1); CPCOMMIT();

    for (int t = 0; t < GKT; t++) {
        CPWAIT1();
        __syncthreads();

        const uint32_t stg = sb + (uint32_t)((t & 1) * STG_B);
#pragma unroll
        for (int ks = 0; ks < 2; ks++) {
            uint32_t ah[4][4];
#pragma unroll
            for (int mt = 0; mt < 4; mt++)
                ldsm4(ah[mt], stg + 0 * ARR_B + aoff + mt * 1280 + ks * 32);
            uint32_t bh[4][2], bl[4][2];
#pragma unroll
            for (int bt = 0; bt < 2; bt++) {
                uint32_t tmp[4];
                ldsm4(tmp, stg + 1 * ARR_B + boff + bt * 1280 + ks * 32);
                bh[2 * bt][0] = tmp[0]; bh[2 * bt][1] = tmp[1];
                bh[2 * bt + 1][0] = tmp[2]; bh[2 * bt + 1][1] = tmp[3];
                ldsm4(tmp, stg + 2 * ARR_B + boff + bt * 1280 + ks * 32);
                bl[2 * bt][0] = tmp[0]; bl[2 * bt][1] = tmp[1];
                bl[2 * bt + 1][0] = tmp[2]; bl[2 * bt + 1][1] = tmp[3];
            }
#pragma unroll
            for (int mt = 0; mt < 4; mt++)
#pragma unroll
                for (int nt = 0; nt < 4; nt++) {
                    mma16816(acc[mt][nt], ah[mt], bh[nt]);
                    mma16816(acc[mt][nt], ah[mt], bl[nt]);
                }
        }
        __syncthreads();
        if (t + 2 < GKT) G_ISSUE(t + 2);
        CPCOMMIT();
    }
#undef G_ISSUE

    const int gr = lane >> 2;
    const int gc = (lane & 3) * 2;
#pragma unroll
    for (int mt = 0; mt < 4; mt++) {
        const int row = m0 + wm * 64 + mt * 16 + gr;
#pragma unroll
        for (int nt = 0; nt < 4; nt++) {
            const int col = n0 + wn * 32 + nt * 8 + gc;
            const size_t i0 = (size_t)row * D_MODEL + col;
            const size_t i1 = (size_t)(row + 8) * D_MODEL + col;
            if (OUT == 0) {
                *(float2*)&C[i0] = make_float2(acc[mt][nt][0], acc[mt][nt][1]);
                *(float2*)&C[i1] = make_float2(acc[mt][nt][2], acc[mt][nt][3]);
            } else {
                uint32_t hi, lo;
                split2h(acc[mt][nt][0], acc[mt][nt][1], hi, lo);
                *(uint32_t*)(Ch + i0) = hi;
                *(uint32_t*)(Cl + i0) = lo;
                split2h(acc[mt][nt][2], acc[mt][nt][3], hi, lo);
                *(uint32_t*)(Ch + i1) = hi;
                *(uint32_t*)(Cl + i1) = lo;
            }
        }
    }
}

// fused QKV projection: blockIdx.z selects weight/output
__global__ __launch_bounds__(256, 2) void gemm_qkv(
    const __half* __restrict__ xh,
    const __half* __restrict__ wqh, const __half* __restrict__ wql,
    const __half* __restrict__ wkh, const __half* __restrict__ wkl,
    const __half* __restrict__ wvh, const __half* __restrict__ wvl,
    __half* __restrict__ qh, __half* __restrict__ ql,
    __half* __restrict__ kh, __half* __restrict__ kl,
    __half* __restrict__ vh, __half* __restrict__ vl) {
    extern __shared__ char smc[];
    const __half *Bh, *Bl;
    __half *Ch, *Cl;
    if (blockIdx.z == 0)      { Bh = wqh; Bl = wql; Ch = qh; Cl = ql; }
    else if (blockIdx.z == 1) { Bh = wkh; Bl = wkl; Ch = kh; Cl = kl; }
    else                      { Bh = wvh; Bl = wvl; Ch = vh; Cl = vl; }
    gemm_body<2>(smc, xh, Bh, Bl, nullptr, Ch, Cl, blockIdx.y * 128, blockIdx.x * 128);
}

__global__ __launch_bounds__(256, 2) void gemm_out(
    const __half* __restrict__ ath,
    const __half* __restrict__ woh, const __half* __restrict__ wol,
    float* __restrict__ out) {
    extern __shared__ char smc[];
    gemm_body<0>(smc, ath, woh, wol, out, nullptr, nullptr, blockIdx.y * 128, blockIdx.x * 128);
}

// ---------------------------------------------------------------------------
// Flash attention on HMMA, fp16 2-pass. Causal.
// 256 threads = 8 warps; Q tile 128 rows (16/warp); KV tiles 64 keys.
// Double-buffered KV stages via cp.async.
// ---------------------------------------------------------------------------
#define FST 144
#define FARR (64 * FST)        // 9216
#define FSTG (4 * FARR)        // Kh | Kl | Vh | Vl = 36864
#define FLASH_SMEM (2 * FSTG)  // 73728

__global__ __launch_bounds__(256) void flash_mma(
    const __half* __restrict__ Qh,
    const __half* __restrict__ Kh, const __half* __restrict__ Kl,
    const __half* __restrict__ Vh, const __half* __restrict__ Vl,
    __half* __restrict__ Oh) {
    extern __shared__ char smc[];
    const uint32_t sb = smem_to_u32(smc);
    const int tid = threadIdx.x;
    const int w = tid >> 5;
    const int lane = tid & 31;
    const int qt = gridDim.x - 1 - blockIdx.x;   // long blocks first
    const int h = blockIdx.y;
    const int b = blockIdx.z;
    const int q0 = qt * 128;
    const int ktmax = 2 * qt + 1;

    const size_t gbase = (size_t)b * SEQL * D_MODEL + h * HEAD_DIM;

    const int r = lane >> 2;
    const int c2 = (lane & 3) * 2;

    // KV staging map: thread -> (array, row)
    const int sa = tid >> 6;           // 0..3
    const int srow = tid & 63;
    const __half* kvsrc =
        (sa == 0 ? Kh : sa == 1 ? Kl : sa == 2 ? Vh : Vl) + gbase + (size_t)srow * D_MODEL;
    const uint32_t kvdst = (uint32_t)(sa * FARR + srow * FST);

    // ldsm lane-address offsets (relative to stage base)
    const uint32_t qaddr = sb + (uint32_t)((w * 16 + (lane & 15)) * FST + (lane >> 4) * 16);
    const uint32_t koff = (uint32_t)(((((lane >> 4) << 3) + (lane & 7)) * FST) + ((lane >> 3) & 1) * 16);
    const uint32_t voff = (uint32_t)((((((lane >> 3) & 1) * 8) + (lane & 7)) * FST) + (lane >> 4) * 16) + 2 * FARR;

    // ---- stage Q (128 rows x 128 B) into buffer 0, grab fragments ----
    {
        const int qrow = tid >> 1;
        const int qhalf = tid & 1;
        const uint32_t d = sb + (uint32_t)(qrow * FST + qhalf * 64);
        const __half* s = Qh + gbase + (size_t)(q0 + qrow) * D_MODEL + qhalf * 32;
#pragma unroll
        for (int j = 0; j < 4; j++) CPA16(d + j * 16, s + j * 8);
    }
    CPCOMMIT(); CPWAIT0();
    __syncthreads();
    uint32_t qhf[4][4];
#pragma unroll
    for (int ks = 0; ks < 4; ks++)
        ldsm4(qhf[ks], qaddr + ks * 32);
    __syncthreads();

#define F_STAGE(kt) do {                                                      \
        const uint32_t d = sb + (uint32_t)(((kt) & 1) * FSTG) + kvdst;        \
        const __half* s = kvsrc + (size_t)(kt) * 64 * D_MODEL;                \
        CPA16(d + 0,   s);      CPA16(d + 16,  s + 8);                        \
        CPA16(d + 32,  s + 16); CPA16(d + 48,  s + 24);                       \
        CPA16(d + 64,  s + 32); CPA16(d + 80,  s + 40);                       \
        CPA16(d + 96,  s + 48); CPA16(d + 112, s + 56);                       \
    } while (0)

    F_STAGE(0); CPCOMMIT();

    float o[8][4];
#pragma unroll
    for (int nt = 0; nt < 8; nt++)
#pragma unroll
        for (int j = 0; j < 4; j++) o[nt][j] = 0.0f;
    float mA = -1e30f, mB = -1e30f, lA = 0.0f, lB = 0.0f;

    for (int kt = 0; kt <= ktmax; kt++) {
        if (kt + 1 <= ktmax) F_STAGE(kt + 1);
        CPCOMMIT();
        CPWAIT1();
        __syncthreads();

        const uint32_t stg = sb + (uint32_t)((kt & 1) * FSTG);
        const int k0 = kt * 64;

        // ---- S = Qh (Kh + Kl)^T ----
        float s[8][4];
#pragma unroll
        for (int nt = 0; nt < 8; nt++)
#pragma unroll
            for (int j = 0; j < 4; j++) s[nt][j] = 0.0f;

#pragma unroll
        for (int ks = 0; ks < 4; ks++) {
#pragma unroll
            for (int np = 0; np < 4; np++) {
                uint32_t th[4], tl[4];
                ldsm4(th, stg + koff + np * 16 * FST + ks * 32);
                ldsm4(tl, stg + FARR + koff + np * 16 * FST + ks * 32);
                mma16816(s[2 * np],     qhf[ks], th);
                mma16816(s[2 * np + 1], qhf[ks], th + 2);
                mma16816(s[2 * np],     qhf[ks], tl);
                mma16816(s[2 * np + 1], qhf[ks], tl + 2);
            }
        }

        // ---- scale + causal mask (only last two kt tiles can cross diag) ----
        const bool masked = (kt >= 2 * qt);
        const int rowA = q0 + w * 16 + r;
        const int rowB = rowA + 8;
#pragma unroll
        for (int nt = 0; nt < 8; nt++)
#pragma unroll
            for (int j = 0; j < 2; j++) {
                const int colg = k0 + nt * 8 + c2 + j;
                float vA = s[nt][j] * 0.125f;
                float vB = s[nt][j + 2] * 0.125f;
                if (masked && colg > rowA) vA = -1e30f;
                if (masked && colg > rowB) vB = -1e30f;
                s[nt][j] = vA;
                s[nt][j + 2] = vB;
            }

        // ---- online softmax ----
        float mxA = -1e30f, mxB = -1e30f;
#pragma unroll
        for (int nt = 0; nt < 8; nt++) {
            mxA = fmaxf(mxA, fmaxf(s[nt][0], s[nt][1]));
            mxB = fmaxf(mxB, fmaxf(s[nt][2], s[nt][3]));
        }
        mxA = fmaxf(mxA, __shfl_xor_sync(0xffffffffu, mxA, 1));
        mxA = fmaxf(mxA, __shfl_xor_sync(0xffffffffu, mxA, 2));
        mxB = fmaxf(mxB, __shfl_xor_sync(0xffffffffu, mxB, 1));
        mxB = fmaxf(mxB, __shfl_xor_sync(0xffffffffu, mxB, 2));
        const float mnA = fmaxf(mA, mxA);
        const float mnB = fmaxf(mB, mxB);
        float suA = 0.0f, suB = 0.0f;
#pragma unroll
        for (int nt = 0; nt < 8; nt++) {
            float e0 = __expf(s[nt][0] - mnA);
            float e1 = __expf(s[nt][1] - mnA);
            float e2 = __expf(s[nt][2] - mnB);
            float e3 = __expf(s[nt][3] - mnB);
            s[nt][0] = e0; s[nt][1] = e1; s[nt][2] = e2; s[nt][3] = e3;
            suA += e0 + e1;
            suB += e2 + e3;
        }
        suA += __shfl_xor_sync(0xffffffffu, suA, 1);
        suA += __shfl_xor_sync(0xffffffffu, suA, 2);
        suB += __shfl_xor_sync(0xffffffffu, suB, 1);
        suB += __shfl_xor_sync(0xffffffffu, suB, 2);
        const float scA = __expf(mA - mnA);
        const float scB = __expf(mB - mnB);
        mA = mnA; mB = mnB;
        lA = lA * scA + suA;
        lB = lB * scB + suB;
#pragma unroll
        for (int nt = 0; nt < 8; nt++) {
            o[nt][0] *= scA; o[nt][1] *= scA;
            o[nt][2] *= scB; o[nt][3] *= scB;
        }

        // ---- O += Ph (Vh + Vl) ----
#pragma unroll
        for (int ks = 0; ks < 4; ks++) {
            uint32_t pha[4];
            pha[0] = packh2(s[2 * ks][0], s[2 * ks][1]);
            pha[1] = packh2(s[2 * ks][2], s[2 * ks][3]);
            pha[2] = packh2(s[2 * ks + 1][0], s[2 * ks + 1][1]);
            pha[3] = packh2(s[2 * ks + 1][2], s[2 * ks + 1][3]);
#pragma unroll
            for (int np = 0; np < 4; np++) {
                uint32_t th[4], tl[4];
                ldsm4t(th, stg + voff + ks * 16 * FST + np * 32);
                ldsm4t(tl, stg + voff + FARR + ks * 16 * FST + np * 32);
                mma16816(o[2 * np],     pha, th);
                mma16816(o[2 * np + 1], pha, th + 2);
                mma16816(o[2 * np],     pha, tl);
                mma16816(o[2 * np + 1], pha, tl + 2);
            }
        }
        __syncthreads();
    }
#undef F_STAGE

    // ---- epilogue: normalize, store fp16 hi ----
    const float liA = 1.0f / lA;
    const float liB = 1.0f / lB;
    const size_t orA = gbase + (size_t)(q0 + w * 16 + r) * D_MODEL;
    const size_t orB = orA + (size_t)8 * D_MODEL;
#pragma unroll
    for (int nt = 0; nt < 8; nt++) {
        const int col = nt * 8 + c2;
        *(uint32_t*)(Oh + orA + col) = packh2(o[nt][0] * liA, o[nt][1] * liA);
        *(uint32_t*)(Oh + orB + col) = packh2(o[nt][2] * liB, o[nt][3] * liB);
    }
}

// ---------------------------------------------------------------------------
extern "C" void kernel_launch(void* const* d_in, const int* in_sizes, int n_in,
                              void* d_out, int out_size) {
    const float* x  = (const float*)d_in[0];
    const float* wq = (const float*)d_in[1];
    const float* wk = (const float*)d_in[2];
    const float* wv = (const float*)d_in[3];
    const float* wo = (const float*)d_in[4];
    float* out = (float*)d_out;

    __half *xh, *qh, *ql, *kh, *kl, *vh, *vl, *ath;
    __half *wqh, *wql, *wkh, *wkl, *wvh, *wvl, *woh, *wol;
    cudaGetSymbolAddress((void**)&xh, g_xh);
    cudaGetSymbolAddress((void**)&qh, g_qh);   cudaGetSymbolAddress((void**)&ql, g_ql);
    cudaGetSymbolAddress((void**)&kh, g_kh);   cudaGetSymbolAddress((void**)&kl, g_kl);
    cudaGetSymbolAddress((void**)&vh, g_vh);   cudaGetSymbolAddress((void**)&vl, g_vl);
    cudaGetSymbolAddress((void**)&ath, g_ath);
    cudaGetSymbolAddress((void**)&wqh, g_wqh); cudaGetSymbolAddress((void**)&wql, g_wql);
    cudaGetSymbolAddress((void**)&wkh, g_wkh); cudaGetSymbolAddress((void**)&wkl, g_wkl);
    cudaGetSymbolAddress((void**)&wvh, g_wvh); cudaGetSymbolAddress((void**)&wvl, g_wvl);
    cudaGetSymbolAddress((void**)&woh, g_woh); cudaGetSymbolAddress((void**)&wol, g_wol);

    cudaFuncSetAttribute(gemm_qkv, cudaFuncAttributeMaxDynamicSharedMemorySize, GEMM_SMEM);
    cudaFuncSetAttribute(gemm_out, cudaFuncAttributeMaxDynamicSharedMemorySize, GEMM_SMEM);
    cudaFuncSetAttribute(flash_mma, cudaFuncAttributeMaxDynamicSharedMemorySize, FLASH_SMEM);

    const int nx4 = MROWS * D_MODEL / 4;
    const int nw4 = D_MODEL * D_MODEL / 4;

    cvt_h_k<<<(nx4 + 255) / 256, 256>>>((const float4*)x, (uint32_t*)xh, nx4);
    split4_h_k<<<dim3((nw4 + 255) / 256, 4), 256>>>(
        (const float4*)wq, (const float4*)wk, (const float4*)wv, (const float4*)wo,
        (uint32_t*)wqh, (uint32_t*)wql, (uint32_t*)wkh, (uint32_t*)wkl,
        (uint32_t*)wvh, (uint32_t*)wvl, (uint32_t*)woh, (uint32_t*)wol, nw4);

    gemm_qkv<<<dim3(D_MODEL / 128, MROWS / 128, 3), 256, GEMM_SMEM>>>(
        xh, wqh, wql, wkh, wkl, wvh, wvl, qh, ql, kh, kl, vh, vl);

    flash_mma<<<dim3(SEQL / 128, N_HEADS, BATCH), 256, FLASH_SMEM>>>(qh, kh, kl, vh, vl, ath);

    gemm_out<<<dim3(D_MODEL / 128, MROWS / 128), 256, GEMM_SMEM>>>(ath, woh, wol, out);
}

// round 8
// speedup vs baseline: 4.6901x; 1.2907x over previous
#include <cuda_runtime.h>
#include <cuda_fp16.h>
#include <cstdint>
#include <math.h>

#define D_MODEL 1024
#define N_HEADS 16
#define HEAD_DIM 64
#define BATCH 2
#define SEQL 2048
#define MROWS (BATCH * SEQL)   // 4096

// ---------------- scratch (device globals: allocation-free rule) -----------
__device__ __half g_xh[MROWS * D_MODEL];
__device__ __half g_qh[MROWS * D_MODEL];
__device__ __half g_kh[MROWS * D_MODEL];
__device__ __half g_vh[MROWS * D_MODEL];
__device__ __half g_ath[MROWS * D_MODEL];
__device__ __half g_wqh[D_MODEL * D_MODEL];
__device__ __half g_wql[D_MODEL * D_MODEL];
__device__ __half g_wkh[D_MODEL * D_MODEL];
__device__ __half g_wkl[D_MODEL * D_MODEL];
__device__ __half g_wvh[D_MODEL * D_MODEL];
__device__ __half g_wvl[D_MODEL * D_MODEL];
__device__ __half g_woh[D_MODEL * D_MODEL];
__device__ __half g_wol[D_MODEL * D_MODEL];

// ---------------- helpers ---------------------------------------------------
__device__ __forceinline__ uint32_t smem_to_u32(const void* p) {
    uint32_t a;
    asm("{ .reg .u64 t; cvta.to.shared.u64 t, %1; cvt.u32.u64 %0, t; }" : "=r"(a) : "l"(p));
    return a;
}

#define CPA16(dst, src) \
    asm volatile("cp.async.cg.shared.global [%0], [%1], 16;" :: "r"(dst), "l"(src) : "memory")
#define CPCOMMIT() asm volatile("cp.async.commit_group;" ::: "memory")
#define CPWAIT0() asm volatile("cp.async.wait_group 0;" ::: "memory")
#define CPWAIT1() asm volatile("cp.async.wait_group 1;" ::: "memory")

__device__ __forceinline__ void ldsm4(uint32_t* r, uint32_t addr) {
    asm volatile("ldmatrix.sync.aligned.m8n8.x4.shared.b16 {%0,%1,%2,%3}, [%4];"
                 : "=r"(r[0]), "=r"(r[1]), "=r"(r[2]), "=r"(r[3]) : "r"(addr));
}

__device__ __forceinline__ void ldsm4t(uint32_t* r, uint32_t addr) {
    asm volatile("ldmatrix.sync.aligned.m8n8.x4.trans.shared.b16 {%0,%1,%2,%3}, [%4];"
                 : "=r"(r[0]), "=r"(r[1]), "=r"(r[2]), "=r"(r[3]) : "r"(addr));
}

__device__ __forceinline__ void mma16816(float* d, const uint32_t* a, const uint32_t* b) {
    asm volatile(
        "mma.sync.aligned.m16n8k16.row.col.f32.f16.f16.f32 "
        "{%0,%1,%2,%3}, {%4,%5,%6,%7}, {%8,%9}, {%0,%1,%2,%3};"
        : "+f"(d[0]), "+f"(d[1]), "+f"(d[2]), "+f"(d[3])
        : "r"(a[0]), "r"(a[1]), "r"(a[2]), "r"(a[3]), "r"(b[0]), "r"(b[1]));
}

__device__ __forceinline__ uint32_t packh2(float x, float y) {
    __half2 h = __floats2half2_rn(x, y);
    return *(uint32_t*)&h;
}

__device__ __forceinline__ void split2h(float x, float y, uint32_t& hi, uint32_t& lo) {
    __half2 h = __floats2half2_rn(x, y);
    float2 hf = __half22float2(h);
    __half2 l = __floats2half2_rn(x - hf.x, y - hf.y);
    hi = *(uint32_t*)&h;
    lo = *(uint32_t*)&l;
}

// ---------------------------------------------------------------------------
// converts / splits
// ---------------------------------------------------------------------------
__global__ __launch_bounds__(256) void cvt_h_k(const float4* __restrict__ in,
                                               uint32_t* __restrict__ hi, int n4) {
    int i = blockIdx.x * blockDim.x + threadIdx.x;
    if (i >= n4) return;
    float4 v = in[i];
    hi[2 * i]     = packh2(v.x, v.y);
    hi[2 * i + 1] = packh2(v.z, v.w);
}

__global__ __launch_bounds__(256) void split4_h_k(
    const float4* __restrict__ w0, const float4* __restrict__ w1,
    const float4* __restrict__ w2, const float4* __restrict__ w3,
    uint32_t* __restrict__ h0, uint32_t* __restrict__ l0,
    uint32_t* __restrict__ h1, uint32_t* __restrict__ l1,
    uint32_t* __restrict__ h2, uint32_t* __restrict__ l2,
    uint32_t* __restrict__ h3, uint32_t* __restrict__ l3, int n4) {
    int i = blockIdx.x * blockDim.x + threadIdx.x;
    if (i >= n4) return;
    const float4* in; uint32_t* hi; uint32_t* lo;
    switch (blockIdx.y) {
        case 0:  in = w0; hi = h0; lo = l0; break;
        case 1:  in = w1; hi = h1; lo = l1; break;
        case 2:  in = w2; hi = h2; lo = l2; break;
        default: in = w3; hi = h3; lo = l3; break;
    }
    float4 v = in[i];
    uint32_t a0, b0, a1, b1;
    split2h(v.x, v.y, a0, b0);
    split2h(v.z, v.w, a1, b1);
    hi[2 * i] = a0; hi[2 * i + 1] = a1;
    lo[2 * i] = b0; lo[2 * i + 1] = b1;
}

// ---------------------------------------------------------------------------
// HMMA fp16 2-pass GEMM-NT body: C[m,n] = sum_k A[m,k]*(Bh+Bl)[n,k]
// CTA 128x128, BK=32, cp.async double-buffered, 2 CTAs/SM.
// OUT: 0 = fp32 C, 1 = fp16 hi (Ch)
// ---------------------------------------------------------------------------
#define GBK 32
#define GKT (D_MODEL / GBK)          // 32
#define ARR_B 10240                  // 128 rows * 80 B
#define STG_B (3 * ARR_B)            // Ah | Bh | Bl = 30720
#define GEMM_SMEM (2 * STG_B)        // 61440

template <int OUT>
__device__ __forceinline__ void gemm_body(
    char* smc, const __half* __restrict__ Ah,
    const __half* __restrict__ Bh, const __half* __restrict__ Bl,
    float* __restrict__ C, __half* __restrict__ Ch,
    int m0, int n0) {
    const uint32_t sb = smem_to_u32(smc);
    const int tid = threadIdx.x;
    const int wid = tid >> 5;
    const int lane = tid & 31;
    const int wm = wid >> 2;
    const int wn = wid & 3;

    const int lrow = tid >> 1;
    const int lhof = (tid & 1) * 16;
    const __half* pA  = Ah + (size_t)(m0 + lrow) * D_MODEL + lhof;
    const __half* pB1 = Bh + (size_t)(n0 + lrow) * D_MODEL + lhof;
    const __half* pB2 = Bl + (size_t)(n0 + lrow) * D_MODEL + lhof;
    const uint32_t sdst = (uint32_t)(lrow * 80 + (tid & 1) * 32);

    const uint32_t aoff = (uint32_t)((wm * 64 + (lane & 15)) * 80 + (lane >> 4) * 16);
    const int j8 = lane >> 3;
    const uint32_t boff = (uint32_t)((wn * 32 + ((j8 >> 1) << 3) + (lane & 7)) * 80 + (j8 & 1) * 16);

    float acc[4][4][4];
#pragma unroll
    for (int a = 0; a < 4; a++)
#pragma unroll
        for (int b = 0; b < 4; b++)
#pragma unroll
            for (int c = 0; c < 4; c++) acc[a][b][c] = 0.0f;

#define G_ISSUE(s) do {                                                       \
        const uint32_t d = sb + (uint32_t)(((s) & 1) * STG_B) + sdst;         \
        const int go = (s) * GBK;                                             \
        CPA16(d + 0 * ARR_B,      pA  + go);                                  \
        CPA16(d + 0 * ARR_B + 16, pA  + go + 8);                              \
        CPA16(d + 1 * ARR_B,      pB1 + go);                                  \
        CPA16(d + 1 * ARR_B + 16, pB1 + go + 8);                              \
        CPA16(d + 2 * ARR_B,      pB2 + go);                                  \
        CPA16(d + 2 * ARR_B + 16, pB2 + go + 8);                              \
    } while (0)

    G_ISSUE(0); CPCOMMIT();
    G_ISSUE(1); CPCOMMIT();

    for (int t = 0; t < GKT; t++) {
        CPWAIT1();
        __syncthreads();

        const uint32_t stg = sb + (uint32_t)((t & 1) * STG_B);
#pragma unroll
        for (int ks = 0; ks < 2; ks++) {
            uint32_t ah[4][4];
#pragma unroll
            for (int mt = 0; mt < 4; mt++)
                ldsm4(ah[mt], stg + 0 * ARR_B + aoff + mt * 1280 + ks * 32);
            uint32_t bh[4][2], bl[4][2];
#pragma unroll
            for (int bt = 0; bt < 2; bt++) {
                uint32_t tmp[4];
                ldsm4(tmp, stg + 1 * ARR_B + boff + bt * 1280 + ks * 32);
                bh[2 * bt][0] = tmp[0]; bh[2 * bt][1] = tmp[1];
                bh[2 * bt + 1][0] = tmp[2]; bh[2 * bt + 1][1] = tmp[3];
                ldsm4(tmp, stg + 2 * ARR_B + boff + bt * 1280 + ks * 32);
                bl[2 * bt][0] = tmp[0]; bl[2 * bt][1] = tmp[1];
                bl[2 * bt + 1][0] = tmp[2]; bl[2 * bt + 1][1] = tmp[3];
            }
#pragma unroll
            for (int mt = 0; mt < 4; mt++)
#pragma unroll
                for (int nt = 0; nt < 4; nt++) {
                    mma16816(acc[mt][nt], ah[mt], bh[nt]);
                    mma16816(acc[mt][nt], ah[mt], bl[nt]);
                }
        }
        __syncthreads();
        if (t + 2 < GKT) G_ISSUE(t + 2);
        CPCOMMIT();
    }
#undef G_ISSUE

    const int gr = lane >> 2;
    const int gc = (lane & 3) * 2;
#pragma unroll
    for (int mt = 0; mt < 4; mt++) {
        const int row = m0 + wm * 64 + mt * 16 + gr;
#pragma unroll
        for (int nt = 0; nt < 4; nt++) {
            const int col = n0 + wn * 32 + nt * 8 + gc;
            const size_t i0 = (size_t)row * D_MODEL + col;
            const size_t i1 = (size_t)(row + 8) * D_MODEL + col;
            if (OUT == 0) {
                *(float2*)&C[i0] = make_float2(acc[mt][nt][0], acc[mt][nt][1]);
                *(float2*)&C[i1] = make_float2(acc[mt][nt][2], acc[mt][nt][3]);
            } else {
                *(uint32_t*)(Ch + i0) = packh2(acc[mt][nt][0], acc[mt][nt][1]);
                *(uint32_t*)(Ch + i1) = packh2(acc[mt][nt][2], acc[mt][nt][3]);
            }
        }
    }
}

// fused QKV projection: blockIdx.z selects weight/output; fp16-hi outputs
__global__ __launch_bounds__(256, 2) void gemm_qkv(
    const __half* __restrict__ xh,
    const __half* __restrict__ wqh, const __half* __restrict__ wql,
    const __half* __restrict__ wkh, const __half* __restrict__ wkl,
    const __half* __restrict__ wvh, const __half* __restrict__ wvl,
    __half* __restrict__ qh, __half* __restrict__ kh, __half* __restrict__ vh) {
    extern __shared__ char smc[];
    const __half *Bh, *Bl;
    __half *Ch;
    if (blockIdx.z == 0)      { Bh = wqh; Bl = wql; Ch = qh; }
    else if (blockIdx.z == 1) { Bh = wkh; Bl = wkl; Ch = kh; }
    else                      { Bh = wvh; Bl = wvl; Ch = vh; }
    gemm_body<1>(smc, xh, Bh, Bl, nullptr, Ch, blockIdx.y * 128, blockIdx.x * 128);
}

__global__ __launch_bounds__(256, 2) void gemm_out(
    const __half* __restrict__ ath,
    const __half* __restrict__ woh, const __half* __restrict__ wol,
    float* __restrict__ out) {
    extern __shared__ char smc[];
    gemm_body<0>(smc, ath, woh, wol, out, nullptr, blockIdx.y * 128, blockIdx.x * 128);
}

// ---------------------------------------------------------------------------
// Flash attention on HMMA, fp16 hi-only operands. Causal.
// 256 threads = 8 warps; Q tile 128 rows (16/warp); KV tiles 64 keys.
// Double-buffered KV stages (Kh|Vh) via cp.async.
// ---------------------------------------------------------------------------
#define FST 144
#define FARR (64 * FST)        // 9216
#define FSTG (2 * FARR)        // Kh | Vh = 18432
#define FLASH_SMEM (2 * FSTG)  // 36864

__global__ __launch_bounds__(256) void flash_mma(
    const __half* __restrict__ Qh,
    const __half* __restrict__ Kh, const __half* __restrict__ Vh,
    __half* __restrict__ Oh) {
    extern __shared__ char smc[];
    const uint32_t sb = smem_to_u32(smc);
    const int tid = threadIdx.x;
    const int w = tid >> 5;
    const int lane = tid & 31;
    const int qt = gridDim.x - 1 - blockIdx.x;   // long blocks first
    const int h = blockIdx.y;
    const int b = blockIdx.z;
    const int q0 = qt * 128;
    const int ktmax = 2 * qt + 1;

    const size_t gbase = (size_t)b * SEQL * D_MODEL + h * HEAD_DIM;

    const int r = lane >> 2;
    const int c2 = (lane & 3) * 2;

    // KV staging map: 2 arrays (Kh, Vh), 2 threads per 128B row
    const int sa = tid >> 7;            // 0 = Kh, 1 = Vh
    const int t2 = tid & 127;
    const int srow = t2 >> 1;
    const int shalf = t2 & 1;
    const __half* kvsrc = (sa == 0 ? Kh : Vh) + gbase + (size_t)srow * D_MODEL + shalf * 32;
    const uint32_t kvdst = (uint32_t)(sa * FARR + srow * FST + shalf * 64);

    // ldsm lane-address offsets
    const uint32_t qaddr = sb + (uint32_t)((w * 16 + (lane & 15)) * FST + (lane >> 4) * 16);
    const uint32_t koff = (uint32_t)(((((lane >> 4) << 3) + (lane & 7)) * FST) + ((lane >> 3) & 1) * 16);
    const uint32_t voff = (uint32_t)((((((lane >> 3) & 1) * 8) + (lane & 7)) * FST) + (lane >> 4) * 16) + FARR;

    // ---- stage Q (128 rows x 128 B) into buffer 0, grab fragments ----
    {
        const int qrow = tid >> 1;
        const int qhalf = tid & 1;
        const uint32_t d = sb + (uint32_t)(qrow * FST + qhalf * 64);
        const __half* s = Qh + gbase + (size_t)(q0 + qrow) * D_MODEL + qhalf * 32;
#pragma unroll
        for (int j = 0; j < 4; j++) CPA16(d + j * 16, s + j * 8);
    }
    CPCOMMIT(); CPWAIT0();
    __syncthreads();
    uint32_t qhf[4][4];
#pragma unroll
    for (int ks = 0; ks < 4; ks++)
        ldsm4(qhf[ks], qaddr + ks * 32);
    __syncthreads();

#define F_STAGE(kt) do {                                                      \
        const uint32_t d = sb + (uint32_t)(((kt) & 1) * FSTG) + kvdst;        \
        const __half* s = kvsrc + (size_t)(kt) * 64 * D_MODEL;                \
        CPA16(d + 0,  s);      CPA16(d + 16, s + 8);                          \
        CPA16(d + 32, s + 16); CPA16(d + 48, s + 24);                         \
    } while (0)

    F_STAGE(0); CPCOMMIT();

    float o[8][4];
#pragma unroll
    for (int nt = 0; nt < 8; nt++)
#pragma unroll
        for (int j = 0; j < 4; j++) o[nt][j] = 0.0f;
    float mA = -1e30f, mB = -1e30f, lA = 0.0f, lB = 0.0f;

    for (int kt = 0; kt <= ktmax; kt++) {
        if (kt + 1 <= ktmax) F_STAGE(kt + 1);
        CPCOMMIT();
        CPWAIT1();
        __syncthreads();

        const uint32_t stg = sb + (uint32_t)((kt & 1) * FSTG);
        const int k0 = kt * 64;

        // ---- S = Qh Kh^T ----
        float s[8][4];
#pragma unroll
        for (int nt = 0; nt < 8; nt++)
#pragma unroll
            for (int j = 0; j < 4; j++) s[nt][j] = 0.0f;

#pragma unroll
        for (int ks = 0; ks < 4; ks++) {
#pragma unroll
            for (int np = 0; np < 4; np++) {
                uint32_t th[4];
                ldsm4(th, stg + koff + np * 16 * FST + ks * 32);
                mma16816(s[2 * np],     qhf[ks], th);
                mma16816(s[2 * np + 1], qhf[ks], th + 2);
            }
        }

        // ---- scale + causal mask ----
        const bool masked = (kt >= 2 * qt);
        const int rowA = q0 + w * 16 + r;
        const int rowB = rowA + 8;
#pragma unroll
        for (int nt = 0; nt < 8; nt++)
#pragma unroll
            for (int j = 0; j < 2; j++) {
                const int colg = k0 + nt * 8 + c2 + j;
                float vA = s[nt][j] * 0.125f;
                float vB = s[nt][j + 2] * 0.125f;
                if (masked && colg > rowA) vA = -1e30f;
                if (masked && colg > rowB) vB = -1e30f;
                s[nt][j] = vA;
                s[nt][j + 2] = vB;
            }

        // ---- online softmax ----
        float mxA = -1e30f, mxB = -1e30f;
#pragma unroll
        for (int nt = 0; nt < 8; nt++) {
            mxA = fmaxf(mxA, fmaxf(s[nt][0], s[nt][1]));
            mxB = fmaxf(mxB, fmaxf(s[nt][2], s[nt][3]));
        }
        mxA = fmaxf(mxA, __shfl_xor_sync(0xffffffffu, mxA, 1));
        mxA = fmaxf(mxA, __shfl_xor_sync(0xffffffffu, mxA, 2));
        mxB = fmaxf(mxB, __shfl_xor_sync(0xffffffffu, mxB, 1));
        mxB = fmaxf(mxB, __shfl_xor_sync(0xffffffffu, mxB, 2));
        const float mnA = fmaxf(mA, mxA);
        const float mnB = fmaxf(mB, mxB);
        float suA = 0.0f, suB = 0.0f;
#pragma unroll
        for (int nt = 0; nt < 8; nt++) {
            float e0 = __expf(s[nt][0] - mnA);
            float e1 = __expf(s[nt][1] - mnA);
            float e2 = __expf(s[nt][2] - mnB);
            float e3 = __expf(s[nt][3] - mnB);
            s[nt][0] = e0; s[nt][1] = e1; s[nt][2] = e2; s[nt][3] = e3;
            suA += e0 + e1;
            suB += e2 + e3;
        }
        suA += __shfl_xor_sync(0xffffffffu, suA, 1);
        suA += __shfl_xor_sync(0xffffffffu, suA, 2);
        suB += __shfl_xor_sync(0xffffffffu, suB, 1);
        suB += __shfl_xor_sync(0xffffffffu, suB, 2);
        const float scA = __expf(mA - mnA);
        const float scB = __expf(mB - mnB);
        mA = mnA; mB = mnB;
        lA = lA * scA + suA;
        lB = lB * scB + suB;
#pragma unroll
        for (int nt = 0; nt < 8; nt++) {
            o[nt][0] *= scA; o[nt][1] *= scA;
            o[nt][2] *= scB; o[nt][3] *= scB;
        }

        // ---- O += Ph Vh ----
#pragma unroll
        for (int ks = 0; ks < 4; ks++) {
            uint32_t pha[4];
            pha[0] = packh2(s[2 * ks][0], s[2 * ks][1]);
            pha[1] = packh2(s[2 * ks][2], s[2 * ks][3]);
            pha[2] = packh2(s[2 * ks + 1][0], s[2 * ks + 1][1]);
            pha[3] = packh2(s[2 * ks + 1][2], s[2 * ks + 1][3]);
#pragma unroll
            for (int np = 0; np < 4; np++) {
                uint32_t th[4];
                ldsm4t(th, stg + voff + ks * 16 * FST + np * 32);
                mma16816(o[2 * np],     pha, th);
                mma16816(o[2 * np + 1], pha, th + 2);
            }
        }
        __syncthreads();
    }
#undef F_STAGE

    // ---- epilogue: normalize, store fp16 hi ----
    const float liA = 1.0f / lA;
    const float liB = 1.0f / lB;
    const size_t orA = gbase + (size_t)(q0 + w * 16 + r) * D_MODEL;
    const size_t orB = orA + (size_t)8 * D_MODEL;
#pragma unroll
    for (int nt = 0; nt < 8; nt++) {
        const int col = nt * 8 + c2;
        *(uint32_t*)(Oh + orA + col) = packh2(o[nt][0] * liA, o[nt][1] * liA);
        *(uint32_t*)(Oh + orB + col) = packh2(o[nt][2] * liB, o[nt][3] * liB);
    }
}

// ---------------------------------------------------------------------------
extern "C" void kernel_launch(void* const* d_in, const int* in_sizes, int n_in,
                              void* d_out, int out_size) {
    const float* x  = (const float*)d_in[0];
    const float* wq = (const float*)d_in[1];
    const float* wk = (const float*)d_in[2];
    const float* wv = (const float*)d_in[3];
    const float* wo = (const float*)d_in[4];
    float* out = (float*)d_out;

    __half *xh, *qh, *kh, *vh, *ath;
    __half *wqh, *wql, *wkh, *wkl, *wvh, *wvl, *woh, *wol;
    cudaGetSymbolAddress((void**)&xh, g_xh);
    cudaGetSymbolAddress((void**)&qh, g_qh);
    cudaGetSymbolAddress((void**)&kh, g_kh);
    cudaGetSymbolAddress((void**)&vh, g_vh);
    cudaGetSymbolAddress((void**)&ath, g_ath);
    cudaGetSymbolAddress((void**)&wqh, g_wqh); cudaGetSymbolAddress((void**)&wql, g_wql);
    cudaGetSymbolAddress((void**)&wkh, g_wkh); cudaGetSymbolAddress((void**)&wkl, g_wkl);
    cudaGetSymbolAddress((void**)&wvh, g_wvh); cudaGetSymbolAddress((void**)&wvl, g_wvl);
    cudaGetSymbolAddress((void**)&woh, g_woh); cudaGetSymbolAddress((void**)&wol, g_wol);

    cudaFuncSetAttribute(gemm_qkv, cudaFuncAttributeMaxDynamicSharedMemorySize, GEMM_SMEM);
    cudaFuncSetAttribute(gemm_out, cudaFuncAttributeMaxDynamicSharedMemorySize, GEMM_SMEM);
    cudaFuncSetAttribute(flash_mma, cudaFuncAttributeMaxDynamicSharedMemorySize, FLASH_SMEM);

    const int nx4 = MROWS * D_MODEL / 4;
    const int nw4 = D_MODEL * D_MODEL / 4;

    cvt_h_k<<<(nx4 + 255) / 256, 256>>>((const float4*)x, (uint32_t*)xh, nx4);
    split4_h_k<<<dim3((nw4 + 255) / 256, 4), 256>>>(
        (const float4*)wq, (const float4*)wk, (const float4*)wv, (const float4*)wo,
        (uint32_t*)wqh, (uint32_t*)wql, (uint32_t*)wkh, (uint32_t*)wkl,
        (uint32_t*)wvh, (uint32_t*)wvl, (uint32_t*)woh, (uint32_t*)wol, nw4);

    gemm_qkv<<<dim3(D_MODEL / 128, MROWS / 128, 3), 256, GEMM_SMEM>>>(
        xh, wqh, wql, wkh, wkl, wvh, wvl, qh, kh, vh);

    flash_mma<<<dim3(SEQL / 128, N_HEADS, BATCH), 256, FLASH_SMEM>>>(qh, kh, vh, ath);

    gemm_out<<<dim3(D_MODEL / 128, MROWS / 128), 256, GEMM_SMEM>>>(ath, woh, wol, out);
}